// round 5
// baseline (speedup 1.0000x reference)
#include <cuda_runtime.h>
#include <cuda_fp16.h>
#include <cuda_bf16.h>
#include <math.h>
#include <stdint.h>

#define BB 8
#define NN 2048
#define EE 64
#define DD 256
#define ROWS (BB*NN)   // 16384

// ---------------- scratch (static device globals; no allocs) ----------------
__device__ float g_xn[ROWS*EE];
__device__ __align__(16) __half g_q[ROWS*DD];
__device__ __align__(16) __half g_k[ROWS*DD];
__device__ __align__(16) __half g_v[ROWS*DD];
// per-head masked weighted exponents, bf16, A-fragment-major:
// [rowblock16 0..1023][keyblock16-in-batch 0..127][head 0..3][lane 0..31] uint4
__device__ uint4 g_e[(size_t)1024*128*4*32];   // 256MB
__device__ float4 g_il[ROWS];                  // 1/l per head
__device__ float  g_z[ROWS];                   // 1/z
__device__ float g_av[ROWS*DD];
__device__ float g_o1[ROWS*EE];
__device__ float g_Wp[768*64];
__device__ float g_bp[768];

#define CEXP 0.18033688f   // 0.125 * log2(e)

// ---------------- generic helpers ----------------
__device__ __forceinline__ float wsum(float v){
    v += __shfl_xor_sync(0xffffffffu, v, 16);
    v += __shfl_xor_sync(0xffffffffu, v, 8);
    v += __shfl_xor_sync(0xffffffffu, v, 4);
    v += __shfl_xor_sync(0xffffffffu, v, 2);
    v += __shfl_xor_sync(0xffffffffu, v, 1);
    return v;
}
__device__ __forceinline__ float softplusf(float x){
    if (x > 20.f) return x;
    return log1pf(expf(x));
}
__device__ __forceinline__ uint32_t smem_u32(const void* p){
    uint32_t a;
    asm("{ .reg .u64 t; cvta.to.shared.u64 t, %1; cvt.u32.u64 %0, t; }" : "=r"(a) : "l"(p));
    return a;
}
__device__ __forceinline__ float ex2f(float x){
    float r;
    asm("ex2.approx.f32 %0, %1;" : "=f"(r) : "f"(x));
    return r;
}
__device__ __forceinline__ uint32_t packbf2(float a, float b){
    __nv_bfloat162 h = __floats2bfloat162_rn(a, b);
    return *(uint32_t*)&h;
}
__device__ __forceinline__ float bflo(uint32_t u){ return __uint_as_float(u << 16); }
__device__ __forceinline__ float bfhi(uint32_t u){ return __uint_as_float(u & 0xFFFF0000u); }

// ---------------- mma.sync / ldmatrix helpers (baseline PTX, sm_80+) --------
__device__ __forceinline__ void ldm_x4(uint32_t a[4], uint32_t addr){
    asm volatile("ldmatrix.sync.aligned.m8n8.x4.shared.b16 {%0,%1,%2,%3}, [%4];"
        : "=r"(a[0]), "=r"(a[1]), "=r"(a[2]), "=r"(a[3]) : "r"(addr));
}
__device__ __forceinline__ void ldm_x4t(uint32_t a[4], uint32_t addr){
    asm volatile("ldmatrix.sync.aligned.m8n8.x4.trans.shared.b16 {%0,%1,%2,%3}, [%4];"
        : "=r"(a[0]), "=r"(a[1]), "=r"(a[2]), "=r"(a[3]) : "r"(addr));
}
__device__ __forceinline__ void mma16816(float c[4], const uint32_t a[4], const uint32_t b[2]){
    asm volatile("mma.sync.aligned.m16n8k16.row.col.f32.f16.f16.f32 "
        "{%0,%1,%2,%3}, {%4,%5,%6,%7}, {%8,%9}, {%0,%1,%2,%3};"
        : "+f"(c[0]), "+f"(c[1]), "+f"(c[2]), "+f"(c[3])
        : "r"(a[0]), "r"(a[1]), "r"(a[2]), "r"(a[3]), "r"(b[0]), "r"(b[1]));
}

// ---------------- fold: W_eff = m_w @ w_w, b_eff = m_w @ w_b + m_b ----------
__global__ void k_fold(const float* __restrict__ wq_w, const float* __restrict__ wq_b,
                       const float* __restrict__ wk_w, const float* __restrict__ wk_b,
                       const float* __restrict__ wv_w, const float* __restrict__ wv_b,
                       const float* __restrict__ mq_w, const float* __restrict__ mq_b,
                       const float* __restrict__ mk_w, const float* __restrict__ mk_b){
    int r = blockIdx.x, e = threadIdx.x;
    if (r < 256){
        float acc = 0.f;
        for (int c = 0; c < 256; c++) acc += mq_w[r*256+c]*wq_w[c*64+e];
        g_Wp[r*64+e] = acc;
        if (e == 0){
            float bb = mq_b[r];
            for (int c = 0; c < 256; c++) bb += mq_w[r*256+c]*wq_b[c];
            g_bp[r] = bb;
        }
    } else if (r < 512){
        int rr = r - 256;
        float acc = 0.f;
        for (int c = 0; c < 256; c++) acc += mk_w[rr*256+c]*wk_w[c*64+e];
        g_Wp[r*64+e] = acc;
        if (e == 0){
            float bb = mk_b[rr];
            for (int c = 0; c < 256; c++) bb += mk_w[rr*256+c]*wk_b[c];
            g_bp[r] = bb;
        }
    } else {
        int rr = r - 512;
        g_Wp[r*64+e] = wv_w[rr*64+e];
        if (e == 0) g_bp[r] = wv_b[rr];
    }
}

// ---------------- LayerNorm over E=64: one warp per row ----------------
__global__ __launch_bounds__(256) void k_ln(const float* __restrict__ x,
                                            const float* __restrict__ g,
                                            const float* __restrict__ be){
    int t = threadIdx.x, lane = t & 31, w = t >> 5;
    size_t row = (size_t)blockIdx.x*8 + w;
    const float* xr = x + row*64;
    float x0 = xr[lane], x1 = xr[lane+32];
    float mean = wsum(x0+x1)*(1.f/64.f);
    float msq  = wsum(x0*x0+x1*x1)*(1.f/64.f);
    float rs = rsqrtf(msq - mean*mean + 1e-5f);
    float* o = g_xn + row*64;
    o[lane]    = (x0-mean)*rs*g[lane]    + be[lane];
    o[lane+32] = (x1-mean)*rs*g[lane+32] + be[lane+32];
}

// ---------------- QKV GEMM -> fp16 Q/K/V [row][256] --------------------------
__global__ __launch_bounds__(256) void k_qkv(){
    __shared__ float sA[64*68];
    __shared__ float sB[64*68];
    int m0 = blockIdx.x*64, n0 = blockIdx.y*64;
    int t = threadIdx.x;
    for (int i = t; i < 1024; i += 256){
        int r = i >> 4, c = i & 15;
        *(float4*)&sA[r*68 + c*4] = *(const float4*)&g_xn[((size_t)(m0+r))*64 + c*4];
        *(float4*)&sB[r*68 + c*4] = *(const float4*)&g_Wp[(n0+r)*64 + c*4];
    }
    __syncthreads();
    int cg = t & 15, rg = t >> 4;
    float acc[4][4] = {};
    #pragma unroll 4
    for (int e4 = 0; e4 < 16; e4++){
        float4 av[4], bv[4];
        #pragma unroll
        for (int i = 0; i < 4; i++) av[i] = *(const float4*)&sA[(rg+16*i)*68 + e4*4];
        #pragma unroll
        for (int j = 0; j < 4; j++) bv[j] = *(const float4*)&sB[(cg+16*j)*68 + e4*4];
        #pragma unroll
        for (int i = 0; i < 4; i++)
            #pragma unroll
            for (int j = 0; j < 4; j++)
                acc[i][j] += av[i].x*bv[j].x + av[i].y*bv[j].y + av[i].z*bv[j].z + av[i].w*bv[j].w;
    }
    #pragma unroll
    for (int i = 0; i < 4; i++){
        size_t m = m0 + rg + 16*i;
        #pragma unroll
        for (int j = 0; j < 4; j++){
            int n = n0 + cg + 16*j;
            float val = acc[i][j] + g_bp[n];
            if (n < 256)       g_q[m*256 + n]       = __float2half_rn(val);
            else if (n < 512)  g_k[m*256 + (n-256)] = __float2half_rn(val);
            else               g_v[m*256 + (n-512)] = __float2half_rn(val);
        }
    }
}

// ---------------- k_score: single pass -> g_e (bf16 w*exp), g_il, g_z -------
// 512 threads = 16 warps: wq = wid&3 (32-row group), wk = wid>>2 (32-key group)
#define SC_SQO 0
#define SC_SKO 67584
#define SC_SWO 135168
#define SC_SLO 135680
#define SC_SLW 143872
#define SC_SMEM 152064

__global__ void __launch_bounds__(512,1) k_score(const float* __restrict__ gw){
    extern __shared__ char sm[];
    uint32_t sb = smem_u32(sm);
    int t = threadIdx.x, lane = t & 31, wid = t >> 5;
    int t4 = lane & 3, gq = lane >> 2;
    int wq = wid & 3, wk = wid >> 2;
    int b = blockIdx.x >> 4, qt = blockIdx.x & 15;
    size_t qrow0 = (size_t)b*NN + (size_t)qt*128;
    int RB0 = (int)(qrow0 >> 4);
    const char*  qg  = (const char*)(g_q + qrow0*256);
    const char*  kgb = (const char*)(g_k + (size_t)b*NN*256);
    const float* wb  = gw + (size_t)b*NN;
    float* sw = (float*)(sm + SC_SWO);
    float* sL = (float*)(sm + SC_SLO);
    float* sLW = (float*)(sm + SC_SLW);

    // Q tile resident (128 x 512B, pitch 528)
    for (int i = t; i < 4096; i += 512){
        int r = i >> 5, c = i & 31;
        *(uint4*)(sm + SC_SQO + r*528 + c*16) = *(const uint4*)(qg + r*512 + c*16);
    }

    uint32_t lo16 = lane & 15, hi16 = lane >> 4;
    uint32_t aQb = sb + SC_SQO + (uint32_t)(wq*32 + lo16)*528 + hi16*16;
    uint32_t kl  = (uint32_t)((lane & 7) + ((lane >> 4) << 3));
    uint32_t bKb = sb + SC_SKO + (uint32_t)(wk*32)*528 + kl*528 + (uint32_t)((lane >> 3) & 1)*16;

    float lacc[2][2][4], lwac[2][2][4];
    #pragma unroll
    for (int mb = 0; mb < 2; mb++)
        #pragma unroll
        for (int hf = 0; hf < 2; hf++)
            #pragma unroll
            for (int h = 0; h < 4; h++){ lacc[mb][hf][h] = 0.f; lwac[mb][hf][h] = 0.f; }

    for (int j0 = 0; j0 < NN; j0 += 128){
        __syncthreads();
        for (int i = t; i < 4096; i += 512){
            int r = i >> 5, c = i & 31;
            *(uint4*)(sm + SC_SKO + r*528 + c*16) = *(const uint4*)(kgb + (size_t)(j0+r)*512 + c*16);
        }
        if (t < 128) sw[t] = wb[j0 + t];
        __syncthreads();
        #pragma unroll
        for (int h = 0; h < 4; h++){
            float sacc[2][4][4];
            #pragma unroll
            for (int mb = 0; mb < 2; mb++)
                #pragma unroll
                for (int nt = 0; nt < 4; nt++)
                    #pragma unroll
                    for (int q = 0; q < 4; q++) sacc[mb][nt][q] = 0.f;
            #pragma unroll
            for (int ks = 0; ks < 4; ks++){
                uint32_t hk = (uint32_t)(h*64 + ks*16)*2;
                uint32_t aq[2][4];
                ldm_x4(aq[0], aQb + hk);
                ldm_x4(aq[1], aQb + 16u*528 + hk);
                #pragma unroll
                for (int ntp = 0; ntp < 2; ntp++){
                    uint32_t kf[4];
                    ldm_x4(kf, bKb + (uint32_t)(ntp*16)*528 + hk);
                    #pragma unroll
                    for (int mb = 0; mb < 2; mb++){
                        mma16816(sacc[mb][ntp*2],   aq[mb], kf);
                        mma16816(sacc[mb][ntp*2+1], aq[mb], kf+2);
                    }
                }
            }
            #pragma unroll
            for (int mb = 0; mb < 2; mb++){
                size_t RB = (size_t)(RB0 + wq*2 + mb);
                #pragma unroll
                for (int ntp = 0; ntp < 2; ntp++){
                    uint32_t pk[4];
                    #pragma unroll
                    for (int sub = 0; sub < 2; sub++){
                        int nt = ntp*2 + sub;
                        int kloc = wk*32 + nt*8 + 2*t4;
                        float w0 = sw[kloc], w1 = sw[kloc+1];
                        float e0 = ex2f(sacc[mb][nt][0]*CEXP);
                        float e1 = ex2f(sacc[mb][nt][1]*CEXP);
                        float e2 = ex2f(sacc[mb][nt][2]*CEXP);
                        float e3 = ex2f(sacc[mb][nt][3]*CEXP);
                        lacc[mb][0][h] += (w0 != 0.f ? e0 : 0.f) + (w1 != 0.f ? e1 : 0.f);
                        lacc[mb][1][h] += (w0 != 0.f ? e2 : 0.f) + (w1 != 0.f ? e3 : 0.f);
                        float ew0 = e0*w0, ew1 = e1*w1, ew2 = e2*w0, ew3 = e3*w1;
                        lwac[mb][0][h] += ew0 + ew1;
                        lwac[mb][1][h] += ew2 + ew3;
                        pk[sub*2]   = packbf2(ew0, ew1);
                        pk[sub*2+1] = packbf2(ew2, ew3);
                    }
                    int kb = (j0 >> 4) + wk*2 + ntp;
                    g_e[(((RB*128 + (size_t)kb)*4 + (size_t)h) << 5) + lane] =
                        make_uint4(pk[0], pk[1], pk[2], pk[3]);
                }
            }
        }
    }
    // reduce l, lw across t4 quad, then across wk warps
    #pragma unroll
    for (int mb = 0; mb < 2; mb++)
        #pragma unroll
        for (int hf = 0; hf < 2; hf++)
            #pragma unroll
            for (int h = 0; h < 4; h++){
                float v = lacc[mb][hf][h];
                v += __shfl_xor_sync(0xffffffffu, v, 1);
                v += __shfl_xor_sync(0xffffffffu, v, 2);
                float u = lwac[mb][hf][h];
                u += __shfl_xor_sync(0xffffffffu, u, 1);
                u += __shfl_xor_sync(0xffffffffu, u, 2);
                if (t4 == 0){
                    int row = wq*32 + mb*16 + hf*8 + gq;
                    sL[(wk*128 + row)*4 + h] = v;
                    sLW[(wk*128 + row)*4 + h] = u;
                }
            }
    __syncthreads();
    if (wk == 0 && t4 == 0){
        #pragma unroll
        for (int mb = 0; mb < 2; mb++)
            #pragma unroll
            for (int hf = 0; hf < 2; hf++){
                int row = wq*32 + mb*16 + hf*8 + gq;
                float il[4], z = 0.f;
                #pragma unroll
                for (int h = 0; h < 4; h++){
                    float l = sL[row*4+h] + sL[(128+row)*4+h] + sL[(256+row)*4+h] + sL[(384+row)*4+h];
                    float lw = sLW[row*4+h] + sLW[(128+row)*4+h] + sLW[(256+row)*4+h] + sLW[(384+row)*4+h];
                    il[h] = 1.f / l;
                    z += lw * il[h];
                }
                g_il[qrow0 + row] = make_float4(il[0], il[1], il[2], il[3]);
                g_z[qrow0 + row] = 1.f / z;
            }
    }
}

// ---------------- k_av: out = (sum_h il_h * ew_h) @ V / z --------------------
// 512 threads = 16 warps: wq = wid&3 (32-row group), wd = wid>>2 (64-D quarter)
#define AV_SMEM 67584

__device__ __forceinline__ uint32_t mixfrag(uint32_t e0, uint32_t e1, uint32_t e2, uint32_t e3,
                                            const float il[4]){
    float lo = il[0]*bflo(e0) + il[1]*bflo(e1) + il[2]*bflo(e2) + il[3]*bflo(e3);
    float hi = il[0]*bfhi(e0) + il[1]*bfhi(e1) + il[2]*bfhi(e2) + il[3]*bfhi(e3);
    __half2 p = __floats2half2_rn(lo, hi);
    return *(uint32_t*)&p;
}

__global__ void __launch_bounds__(512,1) k_av(){
    extern __shared__ char sm[];
    uint32_t sb = smem_u32(sm);
    int t = threadIdx.x, lane = t & 31, wid = t >> 5;
    int t4 = lane & 3, gq = lane >> 2;
    int wq = wid & 3, wd = wid >> 2;
    size_t row0 = (size_t)blockIdx.x*128;
    int b = blockIdx.x >> 4;
    int RB0 = (int)(row0 >> 4);
    const char* vgb = (const char*)(g_v + (size_t)b*NN*256);

    uint32_t lo16 = lane & 15, hi16 = lane >> 4;
    uint32_t bVb = sb + lo16*528 + (uint32_t)wd*128 + hi16*16;

    // per-row 1/l (4 heads): rows wq*32 + mb*16 + {gq, gq+8}
    float il[2][2][4];
    #pragma unroll
    for (int mb = 0; mb < 2; mb++){
        float4 a = g_il[row0 + (size_t)(wq*32 + mb*16 + gq)];
        il[mb][0][0]=a.x; il[mb][0][1]=a.y; il[mb][0][2]=a.z; il[mb][0][3]=a.w;
        float4 c = g_il[row0 + (size_t)(wq*32 + mb*16 + 8 + gq)];
        il[mb][1][0]=c.x; il[mb][1][1]=c.y; il[mb][1][2]=c.z; il[mb][1][3]=c.w;
    }

    float out[2][8][4];
    #pragma unroll
    for (int mb = 0; mb < 2; mb++)
        #pragma unroll
        for (int nt = 0; nt < 8; nt++)
            #pragma unroll
            for (int q = 0; q < 4; q++) out[mb][nt][q] = 0.f;

    for (int j0 = 0; j0 < NN; j0 += 128){
        __syncthreads();
        for (int i = t; i < 4096; i += 512){
            int r = i >> 5, c = i & 31;
            *(uint4*)(sm + r*528 + c*16) = *(const uint4*)(vgb + (size_t)(j0+r)*512 + c*16);
        }
        __syncthreads();
        #pragma unroll
        for (int ks = 0; ks < 8; ks++){
            int kb = (j0 >> 4) + ks;
            uint32_t aF[2][4];
            #pragma unroll
            for (int mb = 0; mb < 2; mb++){
                const uint4* ep = &g_e[((((size_t)(RB0 + wq*2 + mb)*128 + (size_t)kb)*4) << 5) + lane];
                uint4 u0 = ep[0], u1 = ep[32], u2 = ep[64], u3 = ep[96];
                aF[mb][0] = mixfrag(u0.x, u1.x, u2.x, u3.x, il[mb][0]);
                aF[mb][1] = mixfrag(u0.y, u1.y, u2.y, u3.y, il[mb][1]);
                aF[mb][2] = mixfrag(u0.z, u1.z, u2.z, u3.z, il[mb][0]);
                aF[mb][3] = mixfrag(u0.w, u1.w, u2.w, u3.w, il[mb][1]);
            }
            #pragma unroll
            for (int dt2 = 0; dt2 < 4; dt2++){
                uint32_t vf[4];
                ldm_x4t(vf, bVb + (uint32_t)(ks*16)*528 + (uint32_t)dt2*32);
                mma16816(out[0][dt2*2],   aF[0], vf);
                mma16816(out[0][dt2*2+1], aF[0], vf+2);
                mma16816(out[1][dt2*2],   aF[1], vf);
                mma16816(out[1][dt2*2+1], aF[1], vf+2);
            }
        }
    }
    #pragma unroll
    for (int mb = 0; mb < 2; mb++){
        size_t rA = row0 + (size_t)(wq*32 + mb*16 + gq);
        size_t rB = rA + 8;
        float izA = g_z[rA], izB = g_z[rB];
        #pragma unroll
        for (int nt = 0; nt < 8; nt++){
            int col = wd*64 + nt*8 + 2*t4;
            *(float2*)&g_av[rA*256 + col] = make_float2(out[mb][nt][0]*izA, out[mb][nt][1]*izA);
            *(float2*)&g_av[rB*256 + col] = make_float2(out[mb][nt][2]*izB, out[mb][nt][3]*izB);
        }
    }
}

// ---------------- out1 = x + att_out @ out_w^T + out_b ----------------------
__global__ __launch_bounds__(256) void k_out1(const float* __restrict__ ow,
                                              const float* __restrict__ ob,
                                              const float* __restrict__ x){
    __shared__ float sA[64*68];
    __shared__ float sB[64*68];
    int m0 = blockIdx.x*64;
    int t = threadIdx.x;
    int cg = t & 15, rg = t >> 4;
    float acc[4][4] = {};
    for (int kc = 0; kc < 256; kc += 64){
        __syncthreads();
        for (int i = t; i < 1024; i += 256){
            int r = i >> 4, c = i & 15;
            *(float4*)&sA[r*68 + c*4] = *(const float4*)&g_av[((size_t)(m0+r))*256 + kc + c*4];
            *(float4*)&sB[r*68 + c*4] = *(const float4*)&ow[r*256 + kc + c*4];
        }
        __syncthreads();
        #pragma unroll 4
        for (int e4 = 0; e4 < 16; e4++){
            float4 av[4], bv[4];
            #pragma unroll
            for (int i = 0; i < 4; i++) av[i] = *(const float4*)&sA[(rg+16*i)*68 + e4*4];
            #pragma unroll
            for (int j = 0; j < 4; j++) bv[j] = *(const float4*)&sB[(cg+16*j)*68 + e4*4];
            #pragma unroll
            for (int i = 0; i < 4; i++)
                #pragma unroll
                for (int j = 0; j < 4; j++)
                    acc[i][j] += av[i].x*bv[j].x + av[i].y*bv[j].y + av[i].z*bv[j].z + av[i].w*bv[j].w;
        }
    }
    #pragma unroll
    for (int i = 0; i < 4; i++){
        size_t m = m0 + rg + 16*i;
        #pragma unroll
        for (int j = 0; j < 4; j++){
            int n = cg + 16*j;
            g_o1[m*64 + n] = acc[i][j] + ob[n] + x[m*64 + n];
        }
    }
}

// ---------------- final: out = LN(out1 + softplus(LN(out1)@ffn^T + fb)) -----
__global__ __launch_bounds__(256) void k_final(const float* __restrict__ g,
                                               const float* __restrict__ be,
                                               const float* __restrict__ fw,
                                               const float* __restrict__ fb,
                                               float* __restrict__ out){
    __shared__ float sFW[64*65];
    __shared__ float sy[8][64];
    int t = threadIdx.x, lane = t & 31, w = t >> 5;
    for (int i = t; i < 4096; i += 256) sFW[(i>>6)*65 + (i&63)] = fw[i];
    __syncthreads();
    size_t row = (size_t)blockIdx.x*8 + w;
    const float* o = g_o1 + row*64;
    float o0 = o[lane], o1 = o[lane+32];
    float mean = wsum(o0+o1)*(1.f/64.f);
    float msq  = wsum(o0*o0+o1*o1)*(1.f/64.f);
    float rs = rsqrtf(msq - mean*mean + 1e-5f);
    sy[w][lane]    = (o0-mean)*rs*g[lane]    + be[lane];
    sy[w][lane+32] = (o1-mean)*rs*g[lane+32] + be[lane+32];
    __syncwarp();
    float a0 = fb[lane], a1 = fb[lane+32];
    #pragma unroll 8
    for (int c = 0; c < 64; c++){
        float yv = sy[w][c];
        a0 += yv * sFW[lane*65 + c];
        a1 += yv * sFW[(lane+32)*65 + c];
    }
    float s0 = o0 + softplusf(a0);
    float s1 = o1 + softplusf(a1);
    float m2 = wsum(s0+s1)*(1.f/64.f);
    float q2 = wsum(s0*s0+s1*s1)*(1.f/64.f);
    float r2 = rsqrtf(q2 - m2*m2 + 1e-5f);
    out[row*64 + lane]    = (s0-m2)*r2*g[lane]    + be[lane];
    out[row*64 + lane+32] = (s1-m2)*r2*g[lane+32] + be[lane+32];
}

// ---------------- launch ----------------
extern "C" void kernel_launch(void* const* d_in, const int* in_sizes, int n_in,
                              void* d_out, int out_size){
    (void)in_sizes; (void)n_in; (void)out_size;
    const float* x     = (const float*)d_in[0];
    const float* wts   = (const float*)d_in[1];
    const float* ln_g  = (const float*)d_in[2];
    const float* ln_b  = (const float*)d_in[3];
    const float* wq_w  = (const float*)d_in[4];
    const float* wq_b  = (const float*)d_in[5];
    const float* wk_w  = (const float*)d_in[6];
    const float* wk_b  = (const float*)d_in[7];
    const float* wv_w  = (const float*)d_in[8];
    const float* wv_b  = (const float*)d_in[9];
    const float* mq_w  = (const float*)d_in[10];
    const float* mq_b  = (const float*)d_in[11];
    const float* mk_w  = (const float*)d_in[12];
    const float* mk_b  = (const float*)d_in[13];
    const float* out_w = (const float*)d_in[14];
    const float* out_b = (const float*)d_in[15];
    const float* ffn_w = (const float*)d_in[16];
    const float* ffn_b = (const float*)d_in[17];
    float* out = (float*)d_out;

    cudaFuncSetAttribute(k_score, cudaFuncAttributeMaxDynamicSharedMemorySize, SC_SMEM);
    cudaFuncSetAttribute(k_av,    cudaFuncAttributeMaxDynamicSharedMemorySize, AV_SMEM);

    k_fold<<<768, 64>>>(wq_w, wq_b, wk_w, wk_b, wv_w, wv_b, mq_w, mq_b, mk_w, mk_b);
    k_ln<<<ROWS/8, 256>>>(x, ln_g, ln_b);
    k_qkv<<<dim3(ROWS/64, 12), 256>>>();
    k_score<<<128, 512, SC_SMEM>>>(wts);
    k_av<<<128, 512, AV_SMEM>>>();
    k_out1<<<ROWS/64, 256>>>(out_w, out_b, x);
    k_final<<<ROWS/8, 256>>>(ln_g, ln_b, ffn_w, ffn_b, out);
}

// round 6
// speedup vs baseline: 1.3971x; 1.3971x over previous
#include <cuda_runtime.h>
#include <cuda_fp16.h>
#include <cuda_bf16.h>
#include <math.h>
#include <stdint.h>

#define BB 8
#define NN 2048
#define EE 64
#define DD 256
#define ROWS (BB*NN)   // 16384

// ---------------- scratch (static device globals; no allocs) ----------------
__device__ float g_xn[ROWS*EE];
__device__ __align__(16) __half g_q[ROWS*DD];
__device__ __align__(16) __half g_k[ROWS*DD];
__device__ __align__(16) __half g_v[ROWS*DD];
// per-head masked weighted exponents, bf16, A-fragment-major:
// [rowblock16 0..1023][keyblock16-in-batch 0..127][head 0..3][lane 0..31] uint4
__device__ uint4 g_e[(size_t)1024*128*4*32];   // 256MB
__device__ float4 g_il[ROWS];                  // 1/l per head
__device__ float  g_z[ROWS];                   // 1/z
__device__ float g_av[ROWS*DD];
__device__ float g_o1[ROWS*EE];
__device__ float g_Wp[768*64];
__device__ float g_bp[768];

#define CEXP 0.18033688f   // 0.125 * log2(e)

// ---------------- generic helpers ----------------
__device__ __forceinline__ float wsum(float v){
    v += __shfl_xor_sync(0xffffffffu, v, 16);
    v += __shfl_xor_sync(0xffffffffu, v, 8);
    v += __shfl_xor_sync(0xffffffffu, v, 4);
    v += __shfl_xor_sync(0xffffffffu, v, 2);
    v += __shfl_xor_sync(0xffffffffu, v, 1);
    return v;
}
__device__ __forceinline__ float softplusf(float x){
    if (x > 20.f) return x;
    return log1pf(expf(x));
}
__device__ __forceinline__ uint32_t smem_u32(const void* p){
    uint32_t a;
    asm("{ .reg .u64 t; cvta.to.shared.u64 t, %1; cvt.u32.u64 %0, t; }" : "=r"(a) : "l"(p));
    return a;
}
__device__ __forceinline__ float ex2f(float x){
    float r;
    asm("ex2.approx.f32 %0, %1;" : "=f"(r) : "f"(x));
    return r;
}
__device__ __forceinline__ uint32_t packbf2(float a, float b){
    __nv_bfloat162 h = __floats2bfloat162_rn(a, b);
    return *(uint32_t*)&h;
}
__device__ __forceinline__ float bflo(uint32_t u){ return __uint_as_float(u << 16); }
__device__ __forceinline__ float bfhi(uint32_t u){ return __uint_as_float(u & 0xFFFF0000u); }

// ---------------- mma.sync / ldmatrix helpers (baseline PTX, sm_80+) --------
__device__ __forceinline__ void ldm_x4(uint32_t a[4], uint32_t addr){
    asm volatile("ldmatrix.sync.aligned.m8n8.x4.shared.b16 {%0,%1,%2,%3}, [%4];"
        : "=r"(a[0]), "=r"(a[1]), "=r"(a[2]), "=r"(a[3]) : "r"(addr));
}
__device__ __forceinline__ void ldm_x4t(uint32_t a[4], uint32_t addr){
    asm volatile("ldmatrix.sync.aligned.m8n8.x4.trans.shared.b16 {%0,%1,%2,%3}, [%4];"
        : "=r"(a[0]), "=r"(a[1]), "=r"(a[2]), "=r"(a[3]) : "r"(addr));
}
__device__ __forceinline__ void mma16816(float c[4], const uint32_t a[4], const uint32_t b[2]){
    asm volatile("mma.sync.aligned.m16n8k16.row.col.f32.f16.f16.f32 "
        "{%0,%1,%2,%3}, {%4,%5,%6,%7}, {%8,%9}, {%0,%1,%2,%3};"
        : "+f"(c[0]), "+f"(c[1]), "+f"(c[2]), "+f"(c[3])
        : "r"(a[0]), "r"(a[1]), "r"(a[2]), "r"(a[3]), "r"(b[0]), "r"(b[1]));
}

// ---------------- fold: W_eff = m_w @ w_w, b_eff = m_w @ w_b + m_b ----------
__global__ void k_fold(const float* __restrict__ wq_w, const float* __restrict__ wq_b,
                       const float* __restrict__ wk_w, const float* __restrict__ wk_b,
                       const float* __restrict__ wv_w, const float* __restrict__ wv_b,
                       const float* __restrict__ mq_w, const float* __restrict__ mq_b,
                       const float* __restrict__ mk_w, const float* __restrict__ mk_b){
    int r = blockIdx.x, e = threadIdx.x;
    if (r < 256){
        float acc = 0.f;
        for (int c = 0; c < 256; c++) acc += mq_w[r*256+c]*wq_w[c*64+e];
        g_Wp[r*64+e] = acc;
        if (e == 0){
            float bb = mq_b[r];
            for (int c = 0; c < 256; c++) bb += mq_w[r*256+c]*wq_b[c];
            g_bp[r] = bb;
        }
    } else if (r < 512){
        int rr = r - 256;
        float acc = 0.f;
        for (int c = 0; c < 256; c++) acc += mk_w[rr*256+c]*wk_w[c*64+e];
        g_Wp[r*64+e] = acc;
        if (e == 0){
            float bb = mk_b[rr];
            for (int c = 0; c < 256; c++) bb += mk_w[rr*256+c]*wk_b[c];
            g_bp[r] = bb;
        }
    } else {
        int rr = r - 512;
        g_Wp[r*64+e] = wv_w[rr*64+e];
        if (e == 0) g_bp[r] = wv_b[rr];
    }
}

// ---------------- LayerNorm over E=64: one warp per row ----------------
__global__ __launch_bounds__(256) void k_ln(const float* __restrict__ x,
                                            const float* __restrict__ g,
                                            const float* __restrict__ be){
    int t = threadIdx.x, lane = t & 31, w = t >> 5;
    size_t row = (size_t)blockIdx.x*8 + w;
    const float* xr = x + row*64;
    float x0 = xr[lane], x1 = xr[lane+32];
    float mean = wsum(x0+x1)*(1.f/64.f);
    float msq  = wsum(x0*x0+x1*x1)*(1.f/64.f);
    float rs = rsqrtf(msq - mean*mean + 1e-5f);
    float* o = g_xn + row*64;
    o[lane]    = (x0-mean)*rs*g[lane]    + be[lane];
    o[lane+32] = (x1-mean)*rs*g[lane+32] + be[lane+32];
}

// ---------------- QKV GEMM -> fp16 Q/K/V [row][256] --------------------------
__global__ __launch_bounds__(256) void k_qkv(){
    __shared__ float sA[64*68];
    __shared__ float sB[64*68];
    int m0 = blockIdx.x*64, n0 = blockIdx.y*64;
    int t = threadIdx.x;
    for (int i = t; i < 1024; i += 256){
        int r = i >> 4, c = i & 15;
        *(float4*)&sA[r*68 + c*4] = *(const float4*)&g_xn[((size_t)(m0+r))*64 + c*4];
        *(float4*)&sB[r*68 + c*4] = *(const float4*)&g_Wp[(n0+r)*64 + c*4];
    }
    __syncthreads();
    int cg = t & 15, rg = t >> 4;
    float acc[4][4] = {};
    #pragma unroll 4
    for (int e4 = 0; e4 < 16; e4++){
        float4 av[4], bv[4];
        #pragma unroll
        for (int i = 0; i < 4; i++) av[i] = *(const float4*)&sA[(rg+16*i)*68 + e4*4];
        #pragma unroll
        for (int j = 0; j < 4; j++) bv[j] = *(const float4*)&sB[(cg+16*j)*68 + e4*4];
        #pragma unroll
        for (int i = 0; i < 4; i++)
            #pragma unroll
            for (int j = 0; j < 4; j++)
                acc[i][j] += av[i].x*bv[j].x + av[i].y*bv[j].y + av[i].z*bv[j].z + av[i].w*bv[j].w;
    }
    #pragma unroll
    for (int i = 0; i < 4; i++){
        size_t m = m0 + rg + 16*i;
        #pragma unroll
        for (int j = 0; j < 4; j++){
            int n = n0 + cg + 16*j;
            float val = acc[i][j] + g_bp[n];
            if (n < 256)       g_q[m*256 + n]       = __float2half_rn(val);
            else if (n < 512)  g_k[m*256 + (n-256)] = __float2half_rn(val);
            else               g_v[m*256 + (n-512)] = __float2half_rn(val);
        }
    }
}

// ---------------- k_score: single pass -> g_e (bf16 w*exp), g_il, g_z -------
// 512 threads = 16 warps: wq = wid&3 (32-row group), wk = wid>>2 (32-key group)
#define SC_SQO 0
#define SC_SKO 67584
#define SC_SWO 135168
#define SC_SLO 135680
#define SC_SLW 143872
#define SC_SMEM 152064

__global__ void __launch_bounds__(512,1) k_score(const float* __restrict__ gw){
    extern __shared__ char sm[];
    uint32_t sb = smem_u32(sm);
    int t = threadIdx.x, lane = t & 31, wid = t >> 5;
    int t4 = lane & 3, gq = lane >> 2;
    int wq = wid & 3, wk = wid >> 2;
    int b = blockIdx.x >> 4, qt = blockIdx.x & 15;
    size_t qrow0 = (size_t)b*NN + (size_t)qt*128;
    int RB0 = (int)(qrow0 >> 4);
    const char*  qg  = (const char*)(g_q + qrow0*256);
    const char*  kgb = (const char*)(g_k + (size_t)b*NN*256);
    const float* wb  = gw + (size_t)b*NN;
    float* sw = (float*)(sm + SC_SWO);
    float* sL = (float*)(sm + SC_SLO);
    float* sLW = (float*)(sm + SC_SLW);

    // Q tile resident (128 x 512B, pitch 528)
    for (int i = t; i < 4096; i += 512){
        int r = i >> 5, c = i & 31;
        *(uint4*)(sm + SC_SQO + r*528 + c*16) = *(const uint4*)(qg + r*512 + c*16);
    }

    uint32_t lo16 = lane & 15, hi16 = lane >> 4;
    uint32_t aQb = sb + SC_SQO + (uint32_t)(wq*32 + lo16)*528 + hi16*16;
    uint32_t kl  = (uint32_t)((lane & 7) + ((lane >> 4) << 3));
    uint32_t bKb = sb + SC_SKO + (uint32_t)(wk*32)*528 + kl*528 + (uint32_t)((lane >> 3) & 1)*16;

    float lacc[2][2][4], lwac[2][2][4];
    #pragma unroll
    for (int mb = 0; mb < 2; mb++)
        #pragma unroll
        for (int hf = 0; hf < 2; hf++)
            #pragma unroll
            for (int h = 0; h < 4; h++){ lacc[mb][hf][h] = 0.f; lwac[mb][hf][h] = 0.f; }

    for (int j0 = 0; j0 < NN; j0 += 128){
        __syncthreads();
        for (int i = t; i < 4096; i += 512){
            int r = i >> 5, c = i & 31;
            *(uint4*)(sm + SC_SKO + r*528 + c*16) = *(const uint4*)(kgb + (size_t)(j0+r)*512 + c*16);
        }
        if (t < 128) sw[t] = wb[j0 + t];
        __syncthreads();
        #pragma unroll
        for (int h = 0; h < 4; h++){
            float sacc[2][4][4];
            #pragma unroll
            for (int mb = 0; mb < 2; mb++)
                #pragma unroll
                for (int nt = 0; nt < 4; nt++)
                    #pragma unroll
                    for (int q = 0; q < 4; q++) sacc[mb][nt][q] = 0.f;
            #pragma unroll
            for (int ks = 0; ks < 4; ks++){
                uint32_t hk = (uint32_t)(h*64 + ks*16)*2;
                uint32_t aq[2][4];
                ldm_x4(aq[0], aQb + hk);
                ldm_x4(aq[1], aQb + 16u*528 + hk);
                #pragma unroll
                for (int ntp = 0; ntp < 2; ntp++){
                    uint32_t kf[4];
                    ldm_x4(kf, bKb + (uint32_t)(ntp*16)*528 + hk);
                    #pragma unroll
                    for (int mb = 0; mb < 2; mb++){
                        mma16816(sacc[mb][ntp*2],   aq[mb], kf);
                        mma16816(sacc[mb][ntp*2+1], aq[mb], kf+2);
                    }
                }
            }
            #pragma unroll
            for (int mb = 0; mb < 2; mb++){
                size_t RB = (size_t)(RB0 + wq*2 + mb);
                #pragma unroll
                for (int ntp = 0; ntp < 2; ntp++){
                    uint32_t pk[4];
                    #pragma unroll
                    for (int sub = 0; sub < 2; sub++){
                        int nt = ntp*2 + sub;
                        int kloc = wk*32 + nt*8 + 2*t4;
                        float w0 = sw[kloc], w1 = sw[kloc+1];
                        float e0 = ex2f(sacc[mb][nt][0]*CEXP);
                        float e1 = ex2f(sacc[mb][nt][1]*CEXP);
                        float e2 = ex2f(sacc[mb][nt][2]*CEXP);
                        float e3 = ex2f(sacc[mb][nt][3]*CEXP);
                        lacc[mb][0][h] += (w0 != 0.f ? e0 : 0.f) + (w1 != 0.f ? e1 : 0.f);
                        lacc[mb][1][h] += (w0 != 0.f ? e2 : 0.f) + (w1 != 0.f ? e3 : 0.f);
                        float ew0 = e0*w0, ew1 = e1*w1, ew2 = e2*w0, ew3 = e3*w1;
                        lwac[mb][0][h] += ew0 + ew1;
                        lwac[mb][1][h] += ew2 + ew3;
                        pk[sub*2]   = packbf2(ew0, ew1);
                        pk[sub*2+1] = packbf2(ew2, ew3);
                    }
                    int kb = (j0 >> 4) + wk*2 + ntp;
                    g_e[(((RB*128 + (size_t)kb)*4 + (size_t)h) << 5) + lane] =
                        make_uint4(pk[0], pk[1], pk[2], pk[3]);
                }
            }
        }
    }
    // reduce l, lw across t4 quad, then across wk warps
    #pragma unroll
    for (int mb = 0; mb < 2; mb++)
        #pragma unroll
        for (int hf = 0; hf < 2; hf++)
            #pragma unroll
            for (int h = 0; h < 4; h++){
                float v = lacc[mb][hf][h];
                v += __shfl_xor_sync(0xffffffffu, v, 1);
                v += __shfl_xor_sync(0xffffffffu, v, 2);
                float u = lwac[mb][hf][h];
                u += __shfl_xor_sync(0xffffffffu, u, 1);
                u += __shfl_xor_sync(0xffffffffu, u, 2);
                if (t4 == 0){
                    int row = wq*32 + mb*16 + hf*8 + gq;
                    sL[(wk*128 + row)*4 + h] = v;
                    sLW[(wk*128 + row)*4 + h] = u;
                }
            }
    __syncthreads();
    if (wk == 0 && t4 == 0){
        #pragma unroll
        for (int mb = 0; mb < 2; mb++)
            #pragma unroll
            for (int hf = 0; hf < 2; hf++){
                int row = wq*32 + mb*16 + hf*8 + gq;
                float il[4], z = 0.f;
                #pragma unroll
                for (int h = 0; h < 4; h++){
                    float l = sL[row*4+h] + sL[(128+row)*4+h] + sL[(256+row)*4+h] + sL[(384+row)*4+h];
                    float lw = sLW[row*4+h] + sLW[(128+row)*4+h] + sLW[(256+row)*4+h] + sLW[(384+row)*4+h];
                    il[h] = 1.f / l;
                    z += lw * il[h];
                }
                g_il[qrow0 + row] = make_float4(il[0], il[1], il[2], il[3]);
                g_z[qrow0 + row] = 1.f / z;
            }
    }
}

// ---------------- k_av: cooperative mix -> smem P frags -> HMMA AV ----------
// 512 threads = 16 warps: wq = wid&3 (32-row group), wd = wid>>2 (64-D quarter)
// smem: V tile [128][528B] @0, P frags [64 units][32 lanes] uint4 @67584, il @100352
#define AV_SVO 0
#define AV_SPO 67584
#define AV_SIL 100352
#define AV_SMEM 102400

__device__ __forceinline__ uint32_t mixfrag(uint32_t e0, uint32_t e1, uint32_t e2, uint32_t e3,
                                            float i0, float i1, float i2, float i3){
    float lo = i0*bflo(e0) + i1*bflo(e1) + i2*bflo(e2) + i3*bflo(e3);
    float hi = i0*bfhi(e0) + i1*bfhi(e1) + i2*bfhi(e2) + i3*bfhi(e3);
    __half2 p = __floats2half2_rn(lo, hi);
    return *(uint32_t*)&p;
}

__global__ void __launch_bounds__(512,1) k_av(){
    extern __shared__ char sm[];
    uint32_t sb = smem_u32(sm);
    int t = threadIdx.x, lane = t & 31, wid = t >> 5;
    int t4 = lane & 3, gq = lane >> 2;
    int wq = wid & 3, wd = wid >> 2;
    size_t row0 = (size_t)blockIdx.x*128;
    int b = blockIdx.x >> 4;
    int RB0 = (int)(row0 >> 4);
    const char* vgb = (const char*)(g_v + (size_t)b*NN*256);
    float4* silv = (float4*)(sm + AV_SIL);

    uint32_t lo16 = lane & 15, hi16 = lane >> 4;
    uint32_t bVb = sb + AV_SVO + lo16*528 + (uint32_t)wd*128 + hi16*16;

    if (t < 128) silv[t] = g_il[row0 + (size_t)t];

    float out[2][8][4];
    #pragma unroll
    for (int mb = 0; mb < 2; mb++)
        #pragma unroll
        for (int nt = 0; nt < 8; nt++)
            #pragma unroll
            for (int q = 0; q < 4; q++) out[mb][nt][q] = 0.f;

    for (int j0 = 0; j0 < NN; j0 += 128){
        __syncthreads();
        // V tile
        for (int i = t; i < 4096; i += 512){
            int r = i >> 5, c = i & 31;
            *(uint4*)(sm + AV_SVO + r*528 + c*16) = *(const uint4*)(vgb + (size_t)(j0+r)*512 + c*16);
        }
        // cooperative mix: 64 units (RBl 0..7 x kbl 0..7), each computed ONCE
        #pragma unroll
        for (int uu = 0; uu < 4; uu++){
            int u = wid + uu*16;
            int RBl = u >> 3, kbl = u & 7;
            const uint4* ep = &g_e[((((size_t)(RB0 + RBl)*128 + (size_t)((j0 >> 4) + kbl))*4) << 5) + lane];
            uint4 u0 = ep[0], u1 = ep[32], u2 = ep[64], u3 = ep[96];
            float4 a = silv[RBl*16 + gq];
            float4 c = silv[RBl*16 + 8 + gq];
            uint4 o;
            o.x = mixfrag(u0.x, u1.x, u2.x, u3.x, a.x, a.y, a.z, a.w);
            o.y = mixfrag(u0.y, u1.y, u2.y, u3.y, c.x, c.y, c.z, c.w);
            o.z = mixfrag(u0.z, u1.z, u2.z, u3.z, a.x, a.y, a.z, a.w);
            o.w = mixfrag(u0.w, u1.w, u2.w, u3.w, c.x, c.y, c.z, c.w);
            *(uint4*)(sm + AV_SPO + (u*32 + lane)*16) = o;
        }
        __syncthreads();
        #pragma unroll
        for (int ks = 0; ks < 8; ks++){
            uint32_t aF[2][4];
            #pragma unroll
            for (int mb = 0; mb < 2; mb++){
                uint4 v4 = *(const uint4*)(sm + AV_SPO + ((((wq*2 + mb)*8 + ks)*32 + lane))*16);
                aF[mb][0] = v4.x; aF[mb][1] = v4.y; aF[mb][2] = v4.z; aF[mb][3] = v4.w;
            }
            #pragma unroll
            for (int dt2 = 0; dt2 < 4; dt2++){
                uint32_t vf[4];
                ldm_x4t(vf, bVb + (uint32_t)(ks*16)*528 + (uint32_t)dt2*32);
                mma16816(out[0][dt2*2],   aF[0], vf);
                mma16816(out[0][dt2*2+1], aF[0], vf+2);
                mma16816(out[1][dt2*2],   aF[1], vf);
                mma16816(out[1][dt2*2+1], aF[1], vf+2);
            }
        }
    }
    #pragma unroll
    for (int mb = 0; mb < 2; mb++){
        size_t rA = row0 + (size_t)(wq*32 + mb*16 + gq);
        size_t rB = rA + 8;
        float izA = g_z[rA], izB = g_z[rB];
        #pragma unroll
        for (int nt = 0; nt < 8; nt++){
            int col = wd*64 + nt*8 + 2*t4;
            *(float2*)&g_av[rA*256 + col] = make_float2(out[mb][nt][0]*izA, out[mb][nt][1]*izA);
            *(float2*)&g_av[rB*256 + col] = make_float2(out[mb][nt][2]*izB, out[mb][nt][3]*izB);
        }
    }
}

// ---------------- out1 = x + att_out @ out_w^T + out_b ----------------------
__global__ __launch_bounds__(256) void k_out1(const float* __restrict__ ow,
                                              const float* __restrict__ ob,
                                              const float* __restrict__ x){
    __shared__ float sA[64*68];
    __shared__ float sB[64*68];
    int m0 = blockIdx.x*64;
    int t = threadIdx.x;
    int cg = t & 15, rg = t >> 4;
    float acc[4][4] = {};
    for (int kc = 0; kc < 256; kc += 64){
        __syncthreads();
        for (int i = t; i < 1024; i += 256){
            int r = i >> 4, c = i & 15;
            *(float4*)&sA[r*68 + c*4] = *(const float4*)&g_av[((size_t)(m0+r))*256 + kc + c*4];
            *(float4*)&sB[r*68 + c*4] = *(const float4*)&ow[r*256 + kc + c*4];
        }
        __syncthreads();
        #pragma unroll 4
        for (int e4 = 0; e4 < 16; e4++){
            float4 av[4], bv[4];
            #pragma unroll
            for (int i = 0; i < 4; i++) av[i] = *(const float4*)&sA[(rg+16*i)*68 + e4*4];
            #pragma unroll
            for (int j = 0; j < 4; j++) bv[j] = *(const float4*)&sB[(cg+16*j)*68 + e4*4];
            #pragma unroll
            for (int i = 0; i < 4; i++)
                #pragma unroll
                for (int j = 0; j < 4; j++)
                    acc[i][j] += av[i].x*bv[j].x + av[i].y*bv[j].y + av[i].z*bv[j].z + av[i].w*bv[j].w;
        }
    }
    #pragma unroll
    for (int i = 0; i < 4; i++){
        size_t m = m0 + rg + 16*i;
        #pragma unroll
        for (int j = 0; j < 4; j++){
            int n = cg + 16*j;
            g_o1[m*64 + n] = acc[i][j] + ob[n] + x[m*64 + n];
        }
    }
}

// ---------------- final: out = LN(out1 + softplus(LN(out1)@ffn^T + fb)) -----
__global__ __launch_bounds__(256) void k_final(const float* __restrict__ g,
                                               const float* __restrict__ be,
                                               const float* __restrict__ fw,
                                               const float* __restrict__ fb,
                                               float* __restrict__ out){
    __shared__ float sFW[64*65];
    __shared__ float sy[8][64];
    int t = threadIdx.x, lane = t & 31, w = t >> 5;
    for (int i = t; i < 4096; i += 256) sFW[(i>>6)*65 + (i&63)] = fw[i];
    __syncthreads();
    size_t row = (size_t)blockIdx.x*8 + w;
    const float* o = g_o1 + row*64;
    float o0 = o[lane], o1 = o[lane+32];
    float mean = wsum(o0+o1)*(1.f/64.f);
    float msq  = wsum(o0*o0+o1*o1)*(1.f/64.f);
    float rs = rsqrtf(msq - mean*mean + 1e-5f);
    sy[w][lane]    = (o0-mean)*rs*g[lane]    + be[lane];
    sy[w][lane+32] = (o1-mean)*rs*g[lane+32] + be[lane+32];
    __syncwarp();
    float a0 = fb[lane], a1 = fb[lane+32];
    #pragma unroll 8
    for (int c = 0; c < 64; c++){
        float yv = sy[w][c];
        a0 += yv * sFW[lane*65 + c];
        a1 += yv * sFW[(lane+32)*65 + c];
    }
    float s0 = o0 + softplusf(a0);
    float s1 = o1 + softplusf(a1);
    float m2 = wsum(s0+s1)*(1.f/64.f);
    float q2 = wsum(s0*s0+s1*s1)*(1.f/64.f);
    float r2 = rsqrtf(q2 - m2*m2 + 1e-5f);
    out[row*64 + lane]    = (s0-m2)*r2*g[lane]    + be[lane];
    out[row*64 + lane+32] = (s1-m2)*r2*g[lane+32] + be[lane+32];
}

// ---------------- launch ----------------
extern "C" void kernel_launch(void* const* d_in, const int* in_sizes, int n_in,
                              void* d_out, int out_size){
    (void)in_sizes; (void)n_in; (void)out_size;
    const float* x     = (const float*)d_in[0];
    const float* wts   = (const float*)d_in[1];
    const float* ln_g  = (const float*)d_in[2];
    const float* ln_b  = (const float*)d_in[3];
    const float* wq_w  = (const float*)d_in[4];
    const float* wq_b  = (const float*)d_in[5];
    const float* wk_w  = (const float*)d_in[6];
    const float* wk_b  = (const float*)d_in[7];
    const float* wv_w  = (const float*)d_in[8];
    const float* wv_b  = (const float*)d_in[9];
    const float* mq_w  = (const float*)d_in[10];
    const float* mq_b  = (const float*)d_in[11];
    const float* mk_w  = (const float*)d_in[12];
    const float* mk_b  = (const float*)d_in[13];
    const float* out_w = (const float*)d_in[14];
    const float* out_b = (const float*)d_in[15];
    const float* ffn_w = (const float*)d_in[16];
    const float* ffn_b = (const float*)d_in[17];
    float* out = (float*)d_out;

    cudaFuncSetAttribute(k_score, cudaFuncAttributeMaxDynamicSharedMemorySize, SC_SMEM);
    cudaFuncSetAttribute(k_av,    cudaFuncAttributeMaxDynamicSharedMemorySize, AV_SMEM);

    k_fold<<<768, 64>>>(wq_w, wq_b, wk_w, wk_b, wv_w, wv_b, mq_w, mq_b, mk_w, mk_b);
    k_ln<<<ROWS/8, 256>>>(x, ln_g, ln_b);
    k_qkv<<<dim3(ROWS/64, 12), 256>>>();
    k_score<<<128, 512, SC_SMEM>>>(wts);
    k_av<<<128, 512, AV_SMEM>>>();
    k_out1<<<ROWS/64, 256>>>(out_w, out_b, x);
    k_final<<<ROWS/8, 256>>>(ln_g, ln_b, ffn_w, ffn_b, out);
}

// round 7
// speedup vs baseline: 1.4573x; 1.0431x over previous
#include <cuda_runtime.h>
#include <cuda_fp16.h>
#include <cuda_bf16.h>
#include <math.h>
#include <stdint.h>

#define BB 8
#define NN 2048
#define EE 64
#define DD 256
#define ROWS (BB*NN)   // 16384

// ---------------- scratch (static device globals; no allocs) ----------------
__device__ float g_xn[ROWS*EE];
__device__ __align__(16) __half g_q[ROWS*DD];
__device__ __align__(16) __half g_k[ROWS*DD];
__device__ __align__(16) __half g_v[ROWS*DD];
// per-head masked weighted exponents, bf16, A-fragment-major:
// [rowblock16 0..1023][keyblock16-in-batch 0..127][head 0..3][lane 0..31] uint4
__device__ uint4 g_e[(size_t)1024*128*4*32];   // 256MB
__device__ float4 g_il[ROWS];                  // 1/l per head
__device__ float  g_z[ROWS];                   // 1/z
__device__ float g_av[ROWS*DD];
__device__ float g_Wp[768*64];
__device__ float g_bp[768];

#define CEXP 0.18033688f   // 0.125 * log2(e)

// ---------------- generic helpers ----------------
__device__ __forceinline__ float wsum(float v){
    v += __shfl_xor_sync(0xffffffffu, v, 16);
    v += __shfl_xor_sync(0xffffffffu, v, 8);
    v += __shfl_xor_sync(0xffffffffu, v, 4);
    v += __shfl_xor_sync(0xffffffffu, v, 2);
    v += __shfl_xor_sync(0xffffffffu, v, 1);
    return v;
}
__device__ __forceinline__ float softplusf(float x){
    if (x > 20.f) return x;
    return log1pf(expf(x));
}
__device__ __forceinline__ uint32_t smem_u32(const void* p){
    uint32_t a;
    asm("{ .reg .u64 t; cvta.to.shared.u64 t, %1; cvt.u32.u64 %0, t; }" : "=r"(a) : "l"(p));
    return a;
}
__device__ __forceinline__ float ex2f(float x){
    float r;
    asm("ex2.approx.f32 %0, %1;" : "=f"(r) : "f"(x));
    return r;
}
__device__ __forceinline__ uint32_t packbf2(float a, float b){
    __nv_bfloat162 h = __floats2bfloat162_rn(a, b);
    return *(uint32_t*)&h;
}
__device__ __forceinline__ float bflo(uint32_t u){ return __uint_as_float(u << 16); }
__device__ __forceinline__ float bfhi(uint32_t u){ return __uint_as_float(u & 0xFFFF0000u); }

// ---------------- cp.async helpers (sm_80+ baseline) ----------------
__device__ __forceinline__ void cpa16(uint32_t dst, const void* src){
    asm volatile("cp.async.cg.shared.global [%0], [%1], 16;" :: "r"(dst), "l"(src) : "memory");
}
__device__ __forceinline__ void cpa4(uint32_t dst, const void* src){
    asm volatile("cp.async.ca.shared.global [%0], [%1], 4;" :: "r"(dst), "l"(src) : "memory");
}
#define CPA_COMMIT() asm volatile("cp.async.commit_group;" ::: "memory")
#define CPA_WAIT(n)  asm volatile("cp.async.wait_group %0;" :: "n"(n) : "memory")

// ---------------- mma.sync / ldmatrix helpers (baseline PTX, sm_80+) --------
__device__ __forceinline__ void ldm_x4(uint32_t a[4], uint32_t addr){
    asm volatile("ldmatrix.sync.aligned.m8n8.x4.shared.b16 {%0,%1,%2,%3}, [%4];"
        : "=r"(a[0]), "=r"(a[1]), "=r"(a[2]), "=r"(a[3]) : "r"(addr));
}
__device__ __forceinline__ void ldm_x4t(uint32_t a[4], uint32_t addr){
    asm volatile("ldmatrix.sync.aligned.m8n8.x4.trans.shared.b16 {%0,%1,%2,%3}, [%4];"
        : "=r"(a[0]), "=r"(a[1]), "=r"(a[2]), "=r"(a[3]) : "r"(addr));
}
__device__ __forceinline__ void mma16816(float c[4], const uint32_t a[4], const uint32_t b[2]){
    asm volatile("mma.sync.aligned.m16n8k16.row.col.f32.f16.f16.f32 "
        "{%0,%1,%2,%3}, {%4,%5,%6,%7}, {%8,%9}, {%0,%1,%2,%3};"
        : "+f"(c[0]), "+f"(c[1]), "+f"(c[2]), "+f"(c[3])
        : "r"(a[0]), "r"(a[1]), "r"(a[2]), "r"(a[3]), "r"(b[0]), "r"(b[1]));
}

// ---------------- fold: W_eff = m_w @ w_w, b_eff = m_w @ w_b + m_b ----------
__global__ void k_fold(const float* __restrict__ wq_w, const float* __restrict__ wq_b,
                       const float* __restrict__ wk_w, const float* __restrict__ wk_b,
                       const float* __restrict__ wv_w, const float* __restrict__ wv_b,
                       const float* __restrict__ mq_w, const float* __restrict__ mq_b,
                       const float* __restrict__ mk_w, const float* __restrict__ mk_b){
    int r = blockIdx.x, e = threadIdx.x;
    if (r < 256){
        float acc = 0.f;
        for (int c = 0; c < 256; c++) acc += mq_w[r*256+c]*wq_w[c*64+e];
        g_Wp[r*64+e] = acc;
        if (e == 0){
            float bb = mq_b[r];
            for (int c = 0; c < 256; c++) bb += mq_w[r*256+c]*wq_b[c];
            g_bp[r] = bb;
        }
    } else if (r < 512){
        int rr = r - 256;
        float acc = 0.f;
        for (int c = 0; c < 256; c++) acc += mk_w[rr*256+c]*wk_w[c*64+e];
        g_Wp[r*64+e] = acc;
        if (e == 0){
            float bb = mk_b[rr];
            for (int c = 0; c < 256; c++) bb += mk_w[rr*256+c]*wk_b[c];
            g_bp[r] = bb;
        }
    } else {
        int rr = r - 512;
        g_Wp[r*64+e] = wv_w[rr*64+e];
        if (e == 0) g_bp[r] = wv_b[rr];
    }
}

// ---------------- LayerNorm over E=64: one warp per row ----------------
__global__ __launch_bounds__(256) void k_ln(const float* __restrict__ x,
                                            const float* __restrict__ g,
                                            const float* __restrict__ be){
    int t = threadIdx.x, lane = t & 31, w = t >> 5;
    size_t row = (size_t)blockIdx.x*8 + w;
    const float* xr = x + row*64;
    float x0 = xr[lane], x1 = xr[lane+32];
    float mean = wsum(x0+x1)*(1.f/64.f);
    float msq  = wsum(x0*x0+x1*x1)*(1.f/64.f);
    float rs = rsqrtf(msq - mean*mean + 1e-5f);
    float* o = g_xn + row*64;
    o[lane]    = (x0-mean)*rs*g[lane]    + be[lane];
    o[lane+32] = (x1-mean)*rs*g[lane+32] + be[lane+32];
}

// ---------------- QKV GEMM -> fp16 Q/K/V [row][256] --------------------------
__global__ __launch_bounds__(256) void k_qkv(){
    __shared__ float sA[64*68];
    __shared__ float sB[64*68];
    int m0 = blockIdx.x*64, n0 = blockIdx.y*64;
    int t = threadIdx.x;
    for (int i = t; i < 1024; i += 256){
        int r = i >> 4, c = i & 15;
        *(float4*)&sA[r*68 + c*4] = *(const float4*)&g_xn[((size_t)(m0+r))*64 + c*4];
        *(float4*)&sB[r*68 + c*4] = *(const float4*)&g_Wp[(n0+r)*64 + c*4];
    }
    __syncthreads();
    int cg = t & 15, rg = t >> 4;
    float acc[4][4] = {};
    #pragma unroll 4
    for (int e4 = 0; e4 < 16; e4++){
        float4 av[4], bv[4];
        #pragma unroll
        for (int i = 0; i < 4; i++) av[i] = *(const float4*)&sA[(rg+16*i)*68 + e4*4];
        #pragma unroll
        for (int j = 0; j < 4; j++) bv[j] = *(const float4*)&sB[(cg+16*j)*68 + e4*4];
        #pragma unroll
        for (int i = 0; i < 4; i++)
            #pragma unroll
            for (int j = 0; j < 4; j++)
                acc[i][j] += av[i].x*bv[j].x + av[i].y*bv[j].y + av[i].z*bv[j].z + av[i].w*bv[j].w;
    }
    #pragma unroll
    for (int i = 0; i < 4; i++){
        size_t m = m0 + rg + 16*i;
        #pragma unroll
        for (int j = 0; j < 4; j++){
            int n = n0 + cg + 16*j;
            float val = acc[i][j] + g_bp[n];
            if (n < 256)       g_q[m*256 + n]       = __float2half_rn(val);
            else if (n < 512)  g_k[m*256 + (n-256)] = __float2half_rn(val);
            else               g_v[m*256 + (n-512)] = __float2half_rn(val);
        }
    }
}

// ---------------- k_score: single pass -> g_e (bf16 w*exp), g_il, g_z -------
// 512 threads = 16 warps: wq = wid&3 (32-row group), wk = wid>>2 (32-key group)
// double-buffered K tiles via cp.async
#define SC_SQO 0
#define SC_SK0 67584
#define SC_SK1 135168
#define SC_SW0 202752
#define SC_SW1 203264
#define SC_SLO 203776
#define SC_SLW 211968
#define SC_SMEM 220160

__global__ void __launch_bounds__(512,1) k_score(const float* __restrict__ gw){
    extern __shared__ char sm[];
    uint32_t sb = smem_u32(sm);
    int t = threadIdx.x, lane = t & 31, wid = t >> 5;
    int t4 = lane & 3, gq = lane >> 2;
    int wq = wid & 3, wk = wid >> 2;
    int b = blockIdx.x >> 4, qt = blockIdx.x & 15;
    size_t qrow0 = (size_t)b*NN + (size_t)qt*128;
    int RB0 = (int)(qrow0 >> 4);
    const char*  qg  = (const char*)(g_q + qrow0*256);
    const char*  kgb = (const char*)(g_k + (size_t)b*NN*256);
    const float* wb  = gw + (size_t)b*NN;
    float* sL = (float*)(sm + SC_SLO);
    float* sLW = (float*)(sm + SC_SLW);

    // prefetch K tile 0 + w tile 0
    {
        for (int i = t; i < 4096; i += 512){
            int r = i >> 5, c = i & 31;
            cpa16(sb + SC_SK0 + r*528 + c*16, kgb + (size_t)r*512 + c*16);
        }
        if (t < 128) cpa4(sb + SC_SW0 + t*4, wb + t);
        CPA_COMMIT();
    }
    // Q tile resident (128 x 512B, pitch 528)
    for (int i = t; i < 4096; i += 512){
        int r = i >> 5, c = i & 31;
        *(uint4*)(sm + SC_SQO + r*528 + c*16) = *(const uint4*)(qg + r*512 + c*16);
    }

    uint32_t lo16 = lane & 15, hi16 = lane >> 4;
    uint32_t aQb = sb + SC_SQO + (uint32_t)(wq*32 + lo16)*528 + hi16*16;
    uint32_t kl  = (uint32_t)((lane & 7) + ((lane >> 4) << 3));

    float lacc[2][2][4], lwac[2][2][4];
    #pragma unroll
    for (int mb = 0; mb < 2; mb++)
        #pragma unroll
        for (int hf = 0; hf < 2; hf++)
            #pragma unroll
            for (int h = 0; h < 4; h++){ lacc[mb][hf][h] = 0.f; lwac[mb][hf][h] = 0.f; }

    for (int jt = 0; jt < 16; jt++){
        uint32_t koff = (jt & 1) ? SC_SK1 : SC_SK0;
        uint32_t woff = (jt & 1) ? SC_SW1 : SC_SW0;
        if (jt < 15){
            uint32_t kn = (jt & 1) ? SC_SK0 : SC_SK1;
            uint32_t wn = (jt & 1) ? SC_SW0 : SC_SW1;
            const char* src = kgb + (size_t)(jt+1)*65536;
            for (int i = t; i < 4096; i += 512){
                int r = i >> 5, c = i & 31;
                cpa16(sb + kn + r*528 + c*16, src + (size_t)r*512 + c*16);
            }
            if (t < 128) cpa4(sb + wn + t*4, wb + (jt+1)*128 + t);
            CPA_COMMIT();
            CPA_WAIT(1);
        } else {
            CPA_WAIT(0);
        }
        __syncthreads();
        const float* sw = (const float*)(sm + woff);
        uint32_t bKb = sb + koff + (uint32_t)(wk*32)*528 + kl*528 + (uint32_t)((lane >> 3) & 1)*16;
        #pragma unroll
        for (int h = 0; h < 4; h++){
            float sacc[2][4][4];
            #pragma unroll
            for (int mb = 0; mb < 2; mb++)
                #pragma unroll
                for (int nt = 0; nt < 4; nt++)
                    #pragma unroll
                    for (int q = 0; q < 4; q++) sacc[mb][nt][q] = 0.f;
            #pragma unroll
            for (int ks = 0; ks < 4; ks++){
                uint32_t hk = (uint32_t)(h*64 + ks*16)*2;
                uint32_t aq[2][4];
                ldm_x4(aq[0], aQb + hk);
                ldm_x4(aq[1], aQb + 16u*528 + hk);
                #pragma unroll
                for (int ntp = 0; ntp < 2; ntp++){
                    uint32_t kf[4];
                    ldm_x4(kf, bKb + (uint32_t)(ntp*16)*528 + hk);
                    #pragma unroll
                    for (int mb = 0; mb < 2; mb++){
                        mma16816(sacc[mb][ntp*2],   aq[mb], kf);
                        mma16816(sacc[mb][ntp*2+1], aq[mb], kf+2);
                    }
                }
            }
            #pragma unroll
            for (int mb = 0; mb < 2; mb++){
                size_t RB = (size_t)(RB0 + wq*2 + mb);
                #pragma unroll
                for (int ntp = 0; ntp < 2; ntp++){
                    uint32_t pk[4];
                    #pragma unroll
                    for (int sub = 0; sub < 2; sub++){
                        int nt = ntp*2 + sub;
                        int kloc = wk*32 + nt*8 + 2*t4;
                        float w0 = sw[kloc], w1 = sw[kloc+1];
                        float e0 = ex2f(sacc[mb][nt][0]*CEXP);
                        float e1 = ex2f(sacc[mb][nt][1]*CEXP);
                        float e2 = ex2f(sacc[mb][nt][2]*CEXP);
                        float e3 = ex2f(sacc[mb][nt][3]*CEXP);
                        lacc[mb][0][h] += (w0 != 0.f ? e0 : 0.f) + (w1 != 0.f ? e1 : 0.f);
                        lacc[mb][1][h] += (w0 != 0.f ? e2 : 0.f) + (w1 != 0.f ? e3 : 0.f);
                        float ew0 = e0*w0, ew1 = e1*w1, ew2 = e2*w0, ew3 = e3*w1;
                        lwac[mb][0][h] += ew0 + ew1;
                        lwac[mb][1][h] += ew2 + ew3;
                        pk[sub*2]   = packbf2(ew0, ew1);
                        pk[sub*2+1] = packbf2(ew2, ew3);
                    }
                    int kb = jt*8 + wk*2 + ntp;
                    g_e[(((RB*128 + (size_t)kb)*4 + (size_t)h) << 5) + lane] =
                        make_uint4(pk[0], pk[1], pk[2], pk[3]);
                }
            }
        }
        __syncthreads();
    }
    // reduce l, lw across t4 quad, then across wk warps
    #pragma unroll
    for (int mb = 0; mb < 2; mb++)
        #pragma unroll
        for (int hf = 0; hf < 2; hf++)
            #pragma unroll
            for (int h = 0; h < 4; h++){
                float v = lacc[mb][hf][h];
                v += __shfl_xor_sync(0xffffffffu, v, 1);
                v += __shfl_xor_sync(0xffffffffu, v, 2);
                float u = lwac[mb][hf][h];
                u += __shfl_xor_sync(0xffffffffu, u, 1);
                u += __shfl_xor_sync(0xffffffffu, u, 2);
                if (t4 == 0){
                    int row = wq*32 + mb*16 + hf*8 + gq;
                    sL[(wk*128 + row)*4 + h] = v;
                    sLW[(wk*128 + row)*4 + h] = u;
                }
            }
    __syncthreads();
    if (wk == 0 && t4 == 0){
        #pragma unroll
        for (int mb = 0; mb < 2; mb++)
            #pragma unroll
            for (int hf = 0; hf < 2; hf++){
                int row = wq*32 + mb*16 + hf*8 + gq;
                float il[4], z = 0.f;
                #pragma unroll
                for (int h = 0; h < 4; h++){
                    float l = sL[row*4+h] + sL[(128+row)*4+h] + sL[(256+row)*4+h] + sL[(384+row)*4+h];
                    float lw = sLW[row*4+h] + sLW[(128+row)*4+h] + sLW[(256+row)*4+h] + sLW[(384+row)*4+h];
                    il[h] = 1.f / l;
                    z += lw * il[h];
                }
                g_il[qrow0 + row] = make_float4(il[0], il[1], il[2], il[3]);
                g_z[qrow0 + row] = 1.f / z;
            }
    }
}

// ---------------- k_av: cooperative mix -> smem P frags -> HMMA AV ----------
// 512 threads = 16 warps: wq = wid&3 (32-row group), wd = wid>>2 (64-D quarter)
// double-buffered V tiles via cp.async
#define AV_SV0 0
#define AV_SV1 67584
#define AV_SPO 135168
#define AV_SIL 167936
#define AV_SMEM 169984

__device__ __forceinline__ uint32_t mixfrag(uint32_t e0, uint32_t e1, uint32_t e2, uint32_t e3,
                                            float i0, float i1, float i2, float i3){
    float lo = i0*bflo(e0) + i1*bflo(e1) + i2*bflo(e2) + i3*bflo(e3);
    float hi = i0*bfhi(e0) + i1*bfhi(e1) + i2*bfhi(e2) + i3*bfhi(e3);
    __half2 p = __floats2half2_rn(lo, hi);
    return *(uint32_t*)&p;
}

__global__ void __launch_bounds__(512,1) k_av(){
    extern __shared__ char sm[];
    uint32_t sb = smem_u32(sm);
    int t = threadIdx.x, lane = t & 31, wid = t >> 5;
    int t4 = lane & 3, gq = lane >> 2;
    int wq = wid & 3, wd = wid >> 2;
    size_t row0 = (size_t)blockIdx.x*128;
    int b = blockIdx.x >> 4;
    int RB0 = (int)(row0 >> 4);
    const char* vgb = (const char*)(g_v + (size_t)b*NN*256);
    float4* silv = (float4*)(sm + AV_SIL);

    // prefetch V tile 0
    for (int i = t; i < 4096; i += 512){
        int r = i >> 5, c = i & 31;
        cpa16(sb + AV_SV0 + r*528 + c*16, vgb + (size_t)r*512 + c*16);
    }
    CPA_COMMIT();

    uint32_t lo16 = lane & 15, hi16 = lane >> 4;
    if (t < 128) silv[t] = g_il[row0 + (size_t)t];

    float out[2][8][4];
    #pragma unroll
    for (int mb = 0; mb < 2; mb++)
        #pragma unroll
        for (int nt = 0; nt < 8; nt++)
            #pragma unroll
            for (int q = 0; q < 4; q++) out[mb][nt][q] = 0.f;

    for (int jt = 0; jt < 16; jt++){
        uint32_t voff = (jt & 1) ? AV_SV1 : AV_SV0;
        if (jt < 15){
            uint32_t vn = (jt & 1) ? AV_SV0 : AV_SV1;
            const char* src = vgb + (size_t)(jt+1)*65536;
            for (int i = t; i < 4096; i += 512){
                int r = i >> 5, c = i & 31;
                cpa16(sb + vn + r*528 + c*16, src + (size_t)r*512 + c*16);
            }
            CPA_COMMIT();
            CPA_WAIT(1);
        } else {
            CPA_WAIT(0);
        }
        __syncthreads();
        // cooperative mix: 64 units (RBl 0..7 x kbl 0..7), each computed ONCE
        #pragma unroll
        for (int uu = 0; uu < 4; uu++){
            int u = wid + uu*16;
            int RBl = u >> 3, kbl = u & 7;
            const uint4* ep = &g_e[((((size_t)(RB0 + RBl)*128 + (size_t)(jt*8 + kbl))*4) << 5) + lane];
            uint4 u0 = ep[0], u1 = ep[32], u2 = ep[64], u3 = ep[96];
            float4 a = silv[RBl*16 + gq];
            float4 c = silv[RBl*16 + 8 + gq];
            uint4 o;
            o.x = mixfrag(u0.x, u1.x, u2.x, u3.x, a.x, a.y, a.z, a.w);
            o.y = mixfrag(u0.y, u1.y, u2.y, u3.y, c.x, c.y, c.z, c.w);
            o.z = mixfrag(u0.z, u1.z, u2.z, u3.z, a.x, a.y, a.z, a.w);
            o.w = mixfrag(u0.w, u1.w, u2.w, u3.w, c.x, c.y, c.z, c.w);
            *(uint4*)(sm + AV_SPO + (u*32 + lane)*16) = o;
        }
        __syncthreads();
        uint32_t bVb = sb + voff + lo16*528 + (uint32_t)wd*128 + hi16*16;
        #pragma unroll
        for (int ks = 0; ks < 8; ks++){
            uint32_t aF[2][4];
            #pragma unroll
            for (int mb = 0; mb < 2; mb++){
                uint4 v4 = *(const uint4*)(sm + AV_SPO + ((((wq*2 + mb)*8 + ks)*32 + lane))*16);
                aF[mb][0] = v4.x; aF[mb][1] = v4.y; aF[mb][2] = v4.z; aF[mb][3] = v4.w;
            }
            #pragma unroll
            for (int dt2 = 0; dt2 < 4; dt2++){
                uint32_t vf[4];
                ldm_x4t(vf, bVb + (uint32_t)(ks*16)*528 + (uint32_t)dt2*32);
                mma16816(out[0][dt2*2],   aF[0], vf);
                mma16816(out[0][dt2*2+1], aF[0], vf+2);
                mma16816(out[1][dt2*2],   aF[1], vf);
                mma16816(out[1][dt2*2+1], aF[1], vf+2);
            }
        }
        __syncthreads();
    }
    #pragma unroll
    for (int mb = 0; mb < 2; mb++){
        size_t rA = row0 + (size_t)(wq*32 + mb*16 + gq);
        size_t rB = rA + 8;
        float izA = g_z[rA], izB = g_z[rB];
        #pragma unroll
        for (int nt = 0; nt < 8; nt++){
            int col = wd*64 + nt*8 + 2*t4;
            *(float2*)&g_av[rA*256 + col] = make_float2(out[mb][nt][0]*izA, out[mb][nt][1]*izA);
            *(float2*)&g_av[rB*256 + col] = make_float2(out[mb][nt][2]*izB, out[mb][nt][3]*izB);
        }
    }
}

// ---------------- k_tail: out1 = x + av@ow^T + ob; out = LN(out1 + sp(LN(out1)@fw^T + fb))
__global__ __launch_bounds__(256) void k_tail(const float* __restrict__ ow,
                                              const float* __restrict__ ob,
                                              const float* __restrict__ x,
                                              const float* __restrict__ g,
                                              const float* __restrict__ be,
                                              const float* __restrict__ fw,
                                              const float* __restrict__ fb,
                                              float* __restrict__ out){
    __shared__ float sA[64*68];
    __shared__ float sB[64*68];
    __shared__ float sy[8][64];
    int m0 = blockIdx.x*64;
    int t = threadIdx.x, lane = t & 31, w = t >> 5;
    int cg = t & 15, rg = t >> 4;
    float acc[4][4] = {};
    for (int kc = 0; kc < 256; kc += 64){
        __syncthreads();
        for (int i = t; i < 1024; i += 256){
            int r = i >> 4, c = i & 15;
            *(float4*)&sA[r*68 + c*4] = *(const float4*)&g_av[((size_t)(m0+r))*256 + kc + c*4];
            *(float4*)&sB[r*68 + c*4] = *(const float4*)&ow[r*256 + kc + c*4];
        }
        __syncthreads();
        #pragma unroll 4
        for (int e4 = 0; e4 < 16; e4++){
            float4 av[4], bv[4];
            #pragma unroll
            for (int i = 0; i < 4; i++) av[i] = *(const float4*)&sA[(rg+16*i)*68 + e4*4];
            #pragma unroll
            for (int j = 0; j < 4; j++) bv[j] = *(const float4*)&sB[(cg+16*j)*68 + e4*4];
            #pragma unroll
            for (int i = 0; i < 4; i++)
                #pragma unroll
                for (int j = 0; j < 4; j++)
                    acc[i][j] += av[i].x*bv[j].x + av[i].y*bv[j].y + av[i].z*bv[j].z + av[i].w*bv[j].w;
        }
    }
    __syncthreads();
    // o1 rows into sA (pitch 68); ffn weights into sB (pitch 65)
    #pragma unroll
    for (int i = 0; i < 4; i++){
        int rl = rg + 16*i;
        size_t m = m0 + rl;
        #pragma unroll
        for (int j = 0; j < 4; j++){
            int n = cg + 16*j;
            sA[rl*68 + n] = acc[i][j] + ob[n] + x[m*64 + n];
        }
    }
    for (int i = t; i < 4096; i += 256) sB[(i>>6)*65 + (i&63)] = fw[i];
    __syncthreads();
    #pragma unroll 1
    for (int rr = 0; rr < 8; rr++){
        int rl = w*8 + rr;
        float o0 = sA[rl*68 + lane], o1 = sA[rl*68 + lane + 32];
        float mean = wsum(o0+o1)*(1.f/64.f);
        float msq  = wsum(o0*o0+o1*o1)*(1.f/64.f);
        float rs = rsqrtf(msq - mean*mean + 1e-5f);
        sy[w][lane]    = (o0-mean)*rs*g[lane]    + be[lane];
        sy[w][lane+32] = (o1-mean)*rs*g[lane+32] + be[lane+32];
        __syncwarp();
        float a0 = fb[lane], a1 = fb[lane+32];
        #pragma unroll 8
        for (int c = 0; c < 64; c++){
            float yv = sy[w][c];
            a0 += yv * sB[lane*65 + c];
            a1 += yv * sB[(lane+32)*65 + c];
        }
        float s0 = o0 + softplusf(a0);
        float s1 = o1 + softplusf(a1);
        float m2 = wsum(s0+s1)*(1.f/64.f);
        float q2 = wsum(s0*s0+s1*s1)*(1.f/64.f);
        float r2 = rsqrtf(q2 - m2*m2 + 1e-5f);
        size_t m = m0 + rl;
        out[m*64 + lane]    = (s0-m2)*r2*g[lane]    + be[lane];
        out[m*64 + lane+32] = (s1-m2)*r2*g[lane+32] + be[lane+32];
        __syncwarp();
    }
}

// ---------------- launch ----------------
extern "C" void kernel_launch(void* const* d_in, const int* in_sizes, int n_in,
                              void* d_out, int out_size){
    (void)in_sizes; (void)n_in; (void)out_size;
    const float* x     = (const float*)d_in[0];
    const float* wts   = (const float*)d_in[1];
    const float* ln_g  = (const float*)d_in[2];
    const float* ln_b  = (const float*)d_in[3];
    const float* wq_w  = (const float*)d_in[4];
    const float* wq_b  = (const float*)d_in[5];
    const float* wk_w  = (const float*)d_in[6];
    const float* wk_b  = (const float*)d_in[7];
    const float* wv_w  = (const float*)d_in[8];
    const float* wv_b  = (const float*)d_in[9];
    const float* mq_w  = (const float*)d_in[10];
    const float* mq_b  = (const float*)d_in[11];
    const float* mk_w  = (const float*)d_in[12];
    const float* mk_b  = (const float*)d_in[13];
    const float* out_w = (const float*)d_in[14];
    const float* out_b = (const float*)d_in[15];
    const float* ffn_w = (const float*)d_in[16];
    const float* ffn_b = (const float*)d_in[17];
    float* out = (float*)d_out;

    cudaFuncSetAttribute(k_score, cudaFuncAttributeMaxDynamicSharedMemorySize, SC_SMEM);
    cudaFuncSetAttribute(k_av,    cudaFuncAttributeMaxDynamicSharedMemorySize, AV_SMEM);

    k_fold<<<768, 64>>>(wq_w, wq_b, wk_w, wk_b, wv_w, wv_b, mq_w, mq_b, mk_w, mk_b);
    k_ln<<<ROWS/8, 256>>>(x, ln_g, ln_b);
    k_qkv<<<dim3(ROWS/64, 12), 256>>>();
    k_score<<<128, 512, SC_SMEM>>>(wts);
    k_av<<<128, 512, AV_SMEM>>>();
    k_tail<<<ROWS/64, 256>>>(out_w, out_b, x, ln_g, ln_b, ffn_w, ffn_b, out);
}

// round 8
// speedup vs baseline: 1.4840x; 1.0183x over previous
#include <cuda_runtime.h>
#include <cuda_fp16.h>
#include <cuda_bf16.h>
#include <math.h>
#include <stdint.h>

#define BB 8
#define NN 2048
#define EE 64
#define DD 256
#define ROWS (BB*NN)   // 16384

// ---------------- scratch (static device globals; no allocs) ----------------
__device__ float g_xn[ROWS*EE];
__device__ __align__(16) __half g_q[ROWS*DD];
__device__ __align__(16) __half g_k[ROWS*DD];
__device__ __align__(16) __half g_v[ROWS*DD];
// per-head masked weighted exponents, bf16, A-fragment-major:
// [rowblock16 0..1023][keyblock16-in-batch 0..127][head 0..3][lane 0..31] uint4
__device__ uint4 g_e[(size_t)1024*128*4*32];   // 256MB
__device__ float4 g_il[ROWS];                  // 1/l per head
__device__ float  g_z[ROWS];                   // 1/z
__device__ float g_av[ROWS*DD];
__device__ float g_Wp[768*64];
__device__ float g_bp[768];

#define CEXP 0.18033688f   // 0.125 * log2(e)

// ---------------- generic helpers ----------------
__device__ __forceinline__ float wsum(float v){
    v += __shfl_xor_sync(0xffffffffu, v, 16);
    v += __shfl_xor_sync(0xffffffffu, v, 8);
    v += __shfl_xor_sync(0xffffffffu, v, 4);
    v += __shfl_xor_sync(0xffffffffu, v, 2);
    v += __shfl_xor_sync(0xffffffffu, v, 1);
    return v;
}
__device__ __forceinline__ float softplusf(float x){
    if (x > 20.f) return x;
    return log1pf(expf(x));
}
__device__ __forceinline__ uint32_t smem_u32(const void* p){
    uint32_t a;
    asm("{ .reg .u64 t; cvta.to.shared.u64 t, %1; cvt.u32.u64 %0, t; }" : "=r"(a) : "l"(p));
    return a;
}
__device__ __forceinline__ float ex2f(float x){
    float r;
    asm("ex2.approx.f32 %0, %1;" : "=f"(r) : "f"(x));
    return r;
}
__device__ __forceinline__ uint32_t packbf2(float a, float b){
    __nv_bfloat162 h = __floats2bfloat162_rn(a, b);
    return *(uint32_t*)&h;
}
__device__ __forceinline__ float bflo(uint32_t u){ return __uint_as_float(u << 16); }
__device__ __forceinline__ float bfhi(uint32_t u){ return __uint_as_float(u & 0xFFFF0000u); }

// ---------------- cp.async helpers (sm_80+ baseline) ----------------
__device__ __forceinline__ void cpa16(uint32_t dst, const void* src){
    asm volatile("cp.async.cg.shared.global [%0], [%1], 16;" :: "r"(dst), "l"(src) : "memory");
}
__device__ __forceinline__ void cpa4(uint32_t dst, const void* src){
    asm volatile("cp.async.ca.shared.global [%0], [%1], 4;" :: "r"(dst), "l"(src) : "memory");
}
#define CPA_COMMIT() asm volatile("cp.async.commit_group;" ::: "memory")
#define CPA_WAIT(n)  asm volatile("cp.async.wait_group %0;" :: "n"(n) : "memory")

// ---------------- mma.sync / ldmatrix helpers (baseline PTX, sm_80+) --------
__device__ __forceinline__ void ldm_x4(uint32_t a[4], uint32_t addr){
    asm volatile("ldmatrix.sync.aligned.m8n8.x4.shared.b16 {%0,%1,%2,%3}, [%4];"
        : "=r"(a[0]), "=r"(a[1]), "=r"(a[2]), "=r"(a[3]) : "r"(addr));
}
__device__ __forceinline__ void ldm_x4t(uint32_t a[4], uint32_t addr){
    asm volatile("ldmatrix.sync.aligned.m8n8.x4.trans.shared.b16 {%0,%1,%2,%3}, [%4];"
        : "=r"(a[0]), "=r"(a[1]), "=r"(a[2]), "=r"(a[3]) : "r"(addr));
}
__device__ __forceinline__ void mma16816(float c[4], const uint32_t a[4], const uint32_t b[2]){
    asm volatile("mma.sync.aligned.m16n8k16.row.col.f32.f16.f16.f32 "
        "{%0,%1,%2,%3}, {%4,%5,%6,%7}, {%8,%9}, {%0,%1,%2,%3};"
        : "+f"(c[0]), "+f"(c[1]), "+f"(c[2]), "+f"(c[3])
        : "r"(a[0]), "r"(a[1]), "r"(a[2]), "r"(a[3]), "r"(b[0]), "r"(b[1]));
}

// ---------------- fold: W_eff = m_w @ w_w, b_eff = m_w @ w_b + m_b ----------
__global__ void k_fold(const float* __restrict__ wq_w, const float* __restrict__ wq_b,
                       const float* __restrict__ wk_w, const float* __restrict__ wk_b,
                       const float* __restrict__ wv_w, const float* __restrict__ wv_b,
                       const float* __restrict__ mq_w, const float* __restrict__ mq_b,
                       const float* __restrict__ mk_w, const float* __restrict__ mk_b){
    int r = blockIdx.x, e = threadIdx.x;
    if (r < 256){
        float acc = 0.f;
        for (int c = 0; c < 256; c++) acc += mq_w[r*256+c]*wq_w[c*64+e];
        g_Wp[r*64+e] = acc;
        if (e == 0){
            float bb = mq_b[r];
            for (int c = 0; c < 256; c++) bb += mq_w[r*256+c]*wq_b[c];
            g_bp[r] = bb;
        }
    } else if (r < 512){
        int rr = r - 256;
        float acc = 0.f;
        for (int c = 0; c < 256; c++) acc += mk_w[rr*256+c]*wk_w[c*64+e];
        g_Wp[r*64+e] = acc;
        if (e == 0){
            float bb = mk_b[rr];
            for (int c = 0; c < 256; c++) bb += mk_w[rr*256+c]*wk_b[c];
            g_bp[r] = bb;
        }
    } else {
        int rr = r - 512;
        g_Wp[r*64+e] = wv_w[rr*64+e];
        if (e == 0) g_bp[r] = wv_b[rr];
    }
}

// ---------------- LayerNorm over E=64: one warp per row ----------------
__global__ __launch_bounds__(256) void k_ln(const float* __restrict__ x,
                                            const float* __restrict__ g,
                                            const float* __restrict__ be){
    int t = threadIdx.x, lane = t & 31, w = t >> 5;
    size_t row = (size_t)blockIdx.x*8 + w;
    const float* xr = x + row*64;
    float x0 = xr[lane], x1 = xr[lane+32];
    float mean = wsum(x0+x1)*(1.f/64.f);
    float msq  = wsum(x0*x0+x1*x1)*(1.f/64.f);
    float rs = rsqrtf(msq - mean*mean + 1e-5f);
    float* o = g_xn + row*64;
    o[lane]    = (x0-mean)*rs*g[lane]    + be[lane];
    o[lane+32] = (x1-mean)*rs*g[lane+32] + be[lane+32];
}

// ---------------- QKV GEMM -> fp16 Q/K/V [row][256] --------------------------
__global__ __launch_bounds__(256) void k_qkv(){
    __shared__ float sA[64*68];
    __shared__ float sB[64*68];
    int m0 = blockIdx.x*64, n0 = blockIdx.y*64;
    int t = threadIdx.x;
    for (int i = t; i < 1024; i += 256){
        int r = i >> 4, c = i & 15;
        *(float4*)&sA[r*68 + c*4] = *(const float4*)&g_xn[((size_t)(m0+r))*64 + c*4];
        *(float4*)&sB[r*68 + c*4] = *(const float4*)&g_Wp[(n0+r)*64 + c*4];
    }
    __syncthreads();
    int cg = t & 15, rg = t >> 4;
    float acc[4][4] = {};
    #pragma unroll 4
    for (int e4 = 0; e4 < 16; e4++){
        float4 av[4], bv[4];
        #pragma unroll
        for (int i = 0; i < 4; i++) av[i] = *(const float4*)&sA[(rg+16*i)*68 + e4*4];
        #pragma unroll
        for (int j = 0; j < 4; j++) bv[j] = *(const float4*)&sB[(cg+16*j)*68 + e4*4];
        #pragma unroll
        for (int i = 0; i < 4; i++)
            #pragma unroll
            for (int j = 0; j < 4; j++)
                acc[i][j] += av[i].x*bv[j].x + av[i].y*bv[j].y + av[i].z*bv[j].z + av[i].w*bv[j].w;
    }
    #pragma unroll
    for (int i = 0; i < 4; i++){
        size_t m = m0 + rg + 16*i;
        #pragma unroll
        for (int j = 0; j < 4; j++){
            int n = n0 + cg + 16*j;
            float val = acc[i][j] + g_bp[n];
            if (n < 256)       g_q[m*256 + n]       = __float2half_rn(val);
            else if (n < 512)  g_k[m*256 + (n-256)] = __float2half_rn(val);
            else               g_v[m*256 + (n-512)] = __float2half_rn(val);
        }
    }
}

// ---------------- k_score: 64-query CTAs, 2 CTAs/SM, grid 256 ----------------
// 256 threads = 8 warps: wq = wid&1 (32-row group), wk = wid>>1 (16-key group)
// key tiles of 64, double-buffered via cp.async
#define SC_SQO 0
#define SC_SK0 33792
#define SC_SK1 67584
#define SC_SW0 101376
#define SC_SW1 101632
#define SC_SLO 101888
#define SC_SLW 105984
#define SC_SMEM 110080

__global__ void __launch_bounds__(256,2) k_score(const float* __restrict__ gw){
    extern __shared__ char sm[];
    uint32_t sb = smem_u32(sm);
    int t = threadIdx.x, lane = t & 31, wid = t >> 5;
    int t4 = lane & 3, gq = lane >> 2;
    int wq = wid & 1, wk = wid >> 1;
    int b = blockIdx.x >> 5, qt = blockIdx.x & 31;
    size_t qrow0 = (size_t)b*NN + (size_t)qt*64;
    int RB0 = (int)(qrow0 >> 4);
    const char*  qg  = (const char*)(g_q + qrow0*256);
    const char*  kgb = (const char*)(g_k + (size_t)b*NN*256);
    const float* wb  = gw + (size_t)b*NN;
    float* sL = (float*)(sm + SC_SLO);
    float* sLW = (float*)(sm + SC_SLW);

    // prefetch K tile 0 + w tile 0
    for (int i = t; i < 2048; i += 256){
        int r = i >> 5, c = i & 31;
        cpa16(sb + SC_SK0 + r*528 + c*16, kgb + (size_t)r*512 + c*16);
    }
    if (t < 64) cpa4(sb + SC_SW0 + t*4, wb + t);
    CPA_COMMIT();
    // Q tile resident (64 x 512B, pitch 528)
    for (int i = t; i < 2048; i += 256){
        int r = i >> 5, c = i & 31;
        *(uint4*)(sm + SC_SQO + r*528 + c*16) = *(const uint4*)(qg + r*512 + c*16);
    }

    uint32_t lo16 = lane & 15, hi16 = lane >> 4;
    uint32_t aQb = sb + SC_SQO + (uint32_t)(wq*32 + lo16)*528 + hi16*16;
    uint32_t kl  = (uint32_t)((lane & 7) + ((lane >> 4) << 3));

    float lacc[2][2][4], lwac[2][2][4];
    #pragma unroll
    for (int mb = 0; mb < 2; mb++)
        #pragma unroll
        for (int hf = 0; hf < 2; hf++)
            #pragma unroll
            for (int h = 0; h < 4; h++){ lacc[mb][hf][h] = 0.f; lwac[mb][hf][h] = 0.f; }

    for (int jt = 0; jt < 32; jt++){
        uint32_t koff = (jt & 1) ? SC_SK1 : SC_SK0;
        uint32_t woff = (jt & 1) ? SC_SW1 : SC_SW0;
        if (jt < 31){
            uint32_t kn = (jt & 1) ? SC_SK0 : SC_SK1;
            uint32_t wn = (jt & 1) ? SC_SW0 : SC_SW1;
            const char* src = kgb + (size_t)(jt+1)*32768;
            for (int i = t; i < 2048; i += 256){
                int r = i >> 5, c = i & 31;
                cpa16(sb + kn + r*528 + c*16, src + (size_t)r*512 + c*16);
            }
            if (t < 64) cpa4(sb + wn + t*4, wb + (jt+1)*64 + t);
            CPA_COMMIT();
            CPA_WAIT(1);
        } else {
            CPA_WAIT(0);
        }
        __syncthreads();
        const float* sw = (const float*)(sm + woff);
        uint32_t bKb = sb + koff + (uint32_t)(wk*16)*528 + kl*528 + (uint32_t)((lane >> 3) & 1)*16;
        #pragma unroll
        for (int h = 0; h < 4; h++){
            float sacc[2][2][4];
            #pragma unroll
            for (int mb = 0; mb < 2; mb++)
                #pragma unroll
                for (int nt = 0; nt < 2; nt++)
                    #pragma unroll
                    for (int q = 0; q < 4; q++) sacc[mb][nt][q] = 0.f;
            #pragma unroll
            for (int ks = 0; ks < 4; ks++){
                uint32_t hk = (uint32_t)(h*64 + ks*16)*2;
                uint32_t aq[2][4];
                ldm_x4(aq[0], aQb + hk);
                ldm_x4(aq[1], aQb + 16u*528 + hk);
                uint32_t kf[4];
                ldm_x4(kf, bKb + hk);
                #pragma unroll
                for (int mb = 0; mb < 2; mb++){
                    mma16816(sacc[mb][0], aq[mb], kf);
                    mma16816(sacc[mb][1], aq[mb], kf+2);
                }
            }
            #pragma unroll
            for (int mb = 0; mb < 2; mb++){
                size_t RB = (size_t)(RB0 + wq*2 + mb);
                uint32_t pk[4];
                #pragma unroll
                for (int nt = 0; nt < 2; nt++){
                    int kloc = wk*16 + nt*8 + 2*t4;
                    float w0 = sw[kloc], w1 = sw[kloc+1];
                    float e0 = ex2f(sacc[mb][nt][0]*CEXP);
                    float e1 = ex2f(sacc[mb][nt][1]*CEXP);
                    float e2 = ex2f(sacc[mb][nt][2]*CEXP);
                    float e3 = ex2f(sacc[mb][nt][3]*CEXP);
                    lacc[mb][0][h] += (w0 != 0.f ? e0 : 0.f) + (w1 != 0.f ? e1 : 0.f);
                    lacc[mb][1][h] += (w0 != 0.f ? e2 : 0.f) + (w1 != 0.f ? e3 : 0.f);
                    float ew0 = e0*w0, ew1 = e1*w1, ew2 = e2*w0, ew3 = e3*w1;
                    lwac[mb][0][h] += ew0 + ew1;
                    lwac[mb][1][h] += ew2 + ew3;
                    pk[nt*2]   = packbf2(ew0, ew1);
                    pk[nt*2+1] = packbf2(ew2, ew3);
                }
                int kb = jt*4 + wk;
                g_e[(((RB*128 + (size_t)kb)*4 + (size_t)h) << 5) + lane] =
                    make_uint4(pk[0], pk[1], pk[2], pk[3]);
            }
        }
        __syncthreads();
    }
    // reduce l, lw across t4 quad, then across 4 wk warp-groups
    #pragma unroll
    for (int mb = 0; mb < 2; mb++)
        #pragma unroll
        for (int hf = 0; hf < 2; hf++)
            #pragma unroll
            for (int h = 0; h < 4; h++){
                float v = lacc[mb][hf][h];
                v += __shfl_xor_sync(0xffffffffu, v, 1);
                v += __shfl_xor_sync(0xffffffffu, v, 2);
                float u = lwac[mb][hf][h];
                u += __shfl_xor_sync(0xffffffffu, u, 1);
                u += __shfl_xor_sync(0xffffffffu, u, 2);
                if (t4 == 0){
                    int row = wq*32 + mb*16 + hf*8 + gq;
                    sL[(wk*64 + row)*4 + h] = v;
                    sLW[(wk*64 + row)*4 + h] = u;
                }
            }
    __syncthreads();
    if (wk == 0 && t4 == 0){
        #pragma unroll
        for (int mb = 0; mb < 2; mb++)
            #pragma unroll
            for (int hf = 0; hf < 2; hf++){
                int row = wq*32 + mb*16 + hf*8 + gq;
                float il[4], z = 0.f;
                #pragma unroll
                for (int h = 0; h < 4; h++){
                    float l = sL[row*4+h] + sL[(64+row)*4+h] + sL[(128+row)*4+h] + sL[(192+row)*4+h];
                    float lw = sLW[row*4+h] + sLW[(64+row)*4+h] + sLW[(128+row)*4+h] + sLW[(192+row)*4+h];
                    il[h] = 1.f / l;
                    z += lw * il[h];
                }
                g_il[qrow0 + row] = make_float4(il[0], il[1], il[2], il[3]);
                g_z[qrow0 + row] = 1.f / z;
            }
    }
}

// ---------------- k_av: 64-row CTAs, 2 CTAs/SM, grid 256 --------------------
// 256 threads = 8 warps: wq = wid&1 (32-row group), wd = wid>>1 (64-D quarter)
// V tiles of 64 keys, double-buffered
#define AV_SV0 0
#define AV_SV1 33792
#define AV_SPO 67584
#define AV_SIL 75776
#define AV_SMEM 76800

__device__ __forceinline__ uint32_t mixfrag(uint32_t e0, uint32_t e1, uint32_t e2, uint32_t e3,
                                            float i0, float i1, float i2, float i3){
    float lo = i0*bflo(e0) + i1*bflo(e1) + i2*bflo(e2) + i3*bflo(e3);
    float hi = i0*bfhi(e0) + i1*bfhi(e1) + i2*bfhi(e2) + i3*bfhi(e3);
    __half2 p = __floats2half2_rn(lo, hi);
    return *(uint32_t*)&p;
}

__global__ void __launch_bounds__(256,2) k_av(){
    extern __shared__ char sm[];
    uint32_t sb = smem_u32(sm);
    int t = threadIdx.x, lane = t & 31, wid = t >> 5;
    int t4 = lane & 3, gq = lane >> 2;
    int wq = wid & 1, wd = wid >> 1;
    size_t row0 = (size_t)blockIdx.x*64;
    int b = blockIdx.x >> 5;
    int RB0 = (int)(row0 >> 4);
    const char* vgb = (const char*)(g_v + (size_t)b*NN*256);
    float4* silv = (float4*)(sm + AV_SIL);

    // prefetch V tile 0
    for (int i = t; i < 2048; i += 256){
        int r = i >> 5, c = i & 31;
        cpa16(sb + AV_SV0 + r*528 + c*16, vgb + (size_t)r*512 + c*16);
    }
    CPA_COMMIT();

    uint32_t lo16 = lane & 15, hi16 = lane >> 4;
    if (t < 64) silv[t] = g_il[row0 + (size_t)t];

    float out[2][8][4];
    #pragma unroll
    for (int mb = 0; mb < 2; mb++)
        #pragma unroll
        for (int nt = 0; nt < 8; nt++)
            #pragma unroll
            for (int q = 0; q < 4; q++) out[mb][nt][q] = 0.f;

    for (int jt = 0; jt < 32; jt++){
        uint32_t voff = (jt & 1) ? AV_SV1 : AV_SV0;
        if (jt < 31){
            uint32_t vn = (jt & 1) ? AV_SV0 : AV_SV1;
            const char* src = vgb + (size_t)(jt+1)*32768;
            for (int i = t; i < 2048; i += 256){
                int r = i >> 5, c = i & 31;
                cpa16(sb + vn + r*528 + c*16, src + (size_t)r*512 + c*16);
            }
            CPA_COMMIT();
            CPA_WAIT(1);
        } else {
            CPA_WAIT(0);
        }
        __syncthreads();
        // cooperative mix: 16 units (RBl 0..3 x kbl 0..3), each computed ONCE
        #pragma unroll
        for (int uu = 0; uu < 2; uu++){
            int u = wid + uu*8;
            int RBl = u >> 2, kbl = u & 3;
            const uint4* ep = &g_e[((((size_t)(RB0 + RBl)*128 + (size_t)(jt*4 + kbl))*4) << 5) + lane];
            uint4 u0 = ep[0], u1 = ep[32], u2 = ep[64], u3 = ep[96];
            float4 a = silv[RBl*16 + gq];
            float4 c = silv[RBl*16 + 8 + gq];
            uint4 o;
            o.x = mixfrag(u0.x, u1.x, u2.x, u3.x, a.x, a.y, a.z, a.w);
            o.y = mixfrag(u0.y, u1.y, u2.y, u3.y, c.x, c.y, c.z, c.w);
            o.z = mixfrag(u0.z, u1.z, u2.z, u3.z, a.x, a.y, a.z, a.w);
            o.w = mixfrag(u0.w, u1.w, u2.w, u3.w, c.x, c.y, c.z, c.w);
            *(uint4*)(sm + AV_SPO + (u*32 + lane)*16) = o;
        }
        __syncthreads();
        uint32_t bVb = sb + voff + lo16*528 + (uint32_t)wd*128 + hi16*16;
        #pragma unroll
        for (int ks = 0; ks < 4; ks++){
            uint32_t aF[2][4];
            #pragma unroll
            for (int mb = 0; mb < 2; mb++){
                uint4 v4 = *(const uint4*)(sm + AV_SPO + ((((wq*2 + mb)*4 + ks)*32 + lane))*16);
                aF[mb][0] = v4.x; aF[mb][1] = v4.y; aF[mb][2] = v4.z; aF[mb][3] = v4.w;
            }
            #pragma unroll
            for (int dt2 = 0; dt2 < 4; dt2++){
                uint32_t vf[4];
                ldm_x4t(vf, bVb + (uint32_t)(ks*16)*528 + (uint32_t)dt2*32);
                mma16816(out[0][dt2*2],   aF[0], vf);
                mma16816(out[0][dt2*2+1], aF[0], vf+2);
                mma16816(out[1][dt2*2],   aF[1], vf);
                mma16816(out[1][dt2*2+1], aF[1], vf+2);
            }
        }
        __syncthreads();
    }
    #pragma unroll
    for (int mb = 0; mb < 2; mb++){
        size_t rA = row0 + (size_t)(wq*32 + mb*16 + gq);
        size_t rB = rA + 8;
        float izA = g_z[rA], izB = g_z[rB];
        #pragma unroll
        for (int nt = 0; nt < 8; nt++){
            int col = wd*64 + nt*8 + 2*t4;
            *(float2*)&g_av[rA*256 + col] = make_float2(out[mb][nt][0]*izA, out[mb][nt][1]*izA);
            *(float2*)&g_av[rB*256 + col] = make_float2(out[mb][nt][2]*izB, out[mb][nt][3]*izB);
        }
    }
}

// ---------------- k_tail: out1 = x + av@ow^T + ob; out = LN(out1 + sp(LN(out1)@fw^T + fb))
__global__ __launch_bounds__(256) void k_tail(const float* __restrict__ ow,
                                              const float* __restrict__ ob,
                                              const float* __restrict__ x,
                                              const float* __restrict__ g,
                                              const float* __restrict__ be,
                                              const float* __restrict__ fw,
                                              const float* __restrict__ fb,
                                              float* __restrict__ out){
    __shared__ float sA[64*68];
    __shared__ float sB[64*68];
    __shared__ float sy[8][64];
    int m0 = blockIdx.x*64;
    int t = threadIdx.x, lane = t & 31, w = t >> 5;
    int cg = t & 15, rg = t >> 4;
    float acc[4][4] = {};
    for (int kc = 0; kc < 256; kc += 64){
        __syncthreads();
        for (int i = t; i < 1024; i += 256){
            int r = i >> 4, c = i & 15;
            *(float4*)&sA[r*68 + c*4] = *(const float4*)&g_av[((size_t)(m0+r))*256 + kc + c*4];
            *(float4*)&sB[r*68 + c*4] = *(const float4*)&ow[r*256 + kc + c*4];
        }
        __syncthreads();
        #pragma unroll 4
        for (int e4 = 0; e4 < 16; e4++){
            float4 av[4], bv[4];
            #pragma unroll
            for (int i = 0; i < 4; i++) av[i] = *(const float4*)&sA[(rg+16*i)*68 + e4*4];
            #pragma unroll
            for (int j = 0; j < 4; j++) bv[j] = *(const float4*)&sB[(cg+16*j)*68 + e4*4];
            #pragma unroll
            for (int i = 0; i < 4; i++)
                #pragma unroll
                for (int j = 0; j < 4; j++)
                    acc[i][j] += av[i].x*bv[j].x + av[i].y*bv[j].y + av[i].z*bv[j].z + av[i].w*bv[j].w;
        }
    }
    __syncthreads();
    #pragma unroll
    for (int i = 0; i < 4; i++){
        int rl = rg + 16*i;
        size_t m = m0 + rl;
        #pragma unroll
        for (int j = 0; j < 4; j++){
            int n = cg + 16*j;
            sA[rl*68 + n] = acc[i][j] + ob[n] + x[m*64 + n];
        }
    }
    for (int i = t; i < 4096; i += 256) sB[(i>>6)*65 + (i&63)] = fw[i];
    __syncthreads();
    #pragma unroll 1
    for (int rr = 0; rr < 8; rr++){
        int rl = w*8 + rr;
        float o0 = sA[rl*68 + lane], o1 = sA[rl*68 + lane + 32];
        float mean = wsum(o0+o1)*(1.f/64.f);
        float msq  = wsum(o0*o0+o1*o1)*(1.f/64.f);
        float rs = rsqrtf(msq - mean*mean + 1e-5f);
        sy[w][lane]    = (o0-mean)*rs*g[lane]    + be[lane];
        sy[w][lane+32] = (o1-mean)*rs*g[lane+32] + be[lane+32];
        __syncwarp();
        float a0 = fb[lane], a1 = fb[lane+32];
        #pragma unroll 8
        for (int c = 0; c < 64; c++){
            float yv = sy[w][c];
            a0 += yv * sB[lane*65 + c];
            a1 += yv * sB[(lane+32)*65 + c];
        }
        float s0 = o0 + softplusf(a0);
        float s1 = o1 + softplusf(a1);
        float m2 = wsum(s0+s1)*(1.f/64.f);
        float q2 = wsum(s0*s0+s1*s1)*(1.f/64.f);
        float r2 = rsqrtf(q2 - m2*m2 + 1e-5f);
        size_t m = m0 + rl;
        out[m*64 + lane]    = (s0-m2)*r2*g[lane]    + be[lane];
        out[m*64 + lane+32] = (s1-m2)*r2*g[lane+32] + be[lane+32];
        __syncwarp();
    }
}

// ---------------- launch ----------------
extern "C" void kernel_launch(void* const* d_in, const int* in_sizes, int n_in,
                              void* d_out, int out_size){
    (void)in_sizes; (void)n_in; (void)out_size;
    const float* x     = (const float*)d_in[0];
    const float* wts   = (const float*)d_in[1];
    const float* ln_g  = (const float*)d_in[2];
    const float* ln_b  = (const float*)d_in[3];
    const float* wq_w  = (const float*)d_in[4];
    const float* wq_b  = (const float*)d_in[5];
    const float* wk_w  = (const float*)d_in[6];
    const float* wk_b  = (const float*)d_in[7];
    const float* wv_w  = (const float*)d_in[8];
    const float* wv_b  = (const float*)d_in[9];
    const float* mq_w  = (const float*)d_in[10];
    const float* mq_b  = (const float*)d_in[11];
    const float* mk_w  = (const float*)d_in[12];
    const float* mk_b  = (const float*)d_in[13];
    const float* out_w = (const float*)d_in[14];
    const float* out_b = (const float*)d_in[15];
    const float* ffn_w = (const float*)d_in[16];
    const float* ffn_b = (const float*)d_in[17];
    float* out = (float*)d_out;

    cudaFuncSetAttribute(k_score, cudaFuncAttributeMaxDynamicSharedMemorySize, SC_SMEM);
    cudaFuncSetAttribute(k_av,    cudaFuncAttributeMaxDynamicSharedMemorySize, AV_SMEM);

    k_fold<<<768, 64>>>(wq_w, wq_b, wk_w, wk_b, wv_w, wv_b, mq_w, mq_b, mk_w, mk_b);
    k_ln<<<ROWS/8, 256>>>(x, ln_g, ln_b);
    k_qkv<<<dim3(ROWS/64, 12), 256>>>();
    k_score<<<256, 256, SC_SMEM>>>(wts);
    k_av<<<256, 256, AV_SMEM>>>();
    k_tail<<<ROWS/64, 256>>>(out_w, out_b, x, ln_g, ln_b, ffn_w, ffn_b, out);
}

// round 9
// speedup vs baseline: 1.6505x; 1.1122x over previous
#include <cuda_runtime.h>
#include <cuda_fp16.h>
#include <cuda_bf16.h>
#include <math.h>
#include <stdint.h>

#define BB 8
#define NN 2048
#define EE 64
#define DD 256
#define ROWS (BB*NN)   // 16384

// ---------------- scratch (static device globals; no allocs) ----------------
__device__ __align__(16) __half g_xh[ROWS*EE];   // LN(x) in fp16
__device__ __align__(16) __half g_q[ROWS*DD];
__device__ __align__(16) __half g_k[ROWS*DD];
__device__ __align__(16) __half g_v[ROWS*DD];
// per-head masked weighted exponents, bf16, A-fragment-major:
// [rowblock16 0..1023][keyblock16-in-batch 0..127][head 0..3][lane 0..31] uint4
__device__ uint4 g_e[(size_t)1024*128*4*32];   // 256MB
__device__ float4 g_il[ROWS];                  // 1/l per head
__device__ float  g_z[ROWS];                   // 1/z
__device__ float g_av[ROWS*DD];
__device__ __align__(16) __half g_Wh[768*64];  // folded qkv weights, fp16
__device__ float g_bp[768];

#define CEXP 0.18033688f   // 0.125 * log2(e)

// ---------------- generic helpers ----------------
__device__ __forceinline__ float wsum(float v){
    v += __shfl_xor_sync(0xffffffffu, v, 16);
    v += __shfl_xor_sync(0xffffffffu, v, 8);
    v += __shfl_xor_sync(0xffffffffu, v, 4);
    v += __shfl_xor_sync(0xffffffffu, v, 2);
    v += __shfl_xor_sync(0xffffffffu, v, 1);
    return v;
}
__device__ __forceinline__ float softplusf(float x){
    if (x > 20.f) return x;
    return log1pf(expf(x));
}
__device__ __forceinline__ uint32_t smem_u32(const void* p){
    uint32_t a;
    asm("{ .reg .u64 t; cvta.to.shared.u64 t, %1; cvt.u32.u64 %0, t; }" : "=r"(a) : "l"(p));
    return a;
}
__device__ __forceinline__ float ex2f(float x){
    float r;
    asm("ex2.approx.f32 %0, %1;" : "=f"(r) : "f"(x));
    return r;
}
__device__ __forceinline__ uint32_t packbf2(float a, float b){
    __nv_bfloat162 h = __floats2bfloat162_rn(a, b);
    return *(uint32_t*)&h;
}
__device__ __forceinline__ float bflo(uint32_t u){ return __uint_as_float(u << 16); }
__device__ __forceinline__ float bfhi(uint32_t u){ return __uint_as_float(u & 0xFFFF0000u); }

// ---------------- cp.async helpers (sm_80+ baseline) ----------------
__device__ __forceinline__ void cpa16(uint32_t dst, const void* src){
    asm volatile("cp.async.cg.shared.global [%0], [%1], 16;" :: "r"(dst), "l"(src) : "memory");
}
__device__ __forceinline__ void cpa4(uint32_t dst, const void* src){
    asm volatile("cp.async.ca.shared.global [%0], [%1], 4;" :: "r"(dst), "l"(src) : "memory");
}
#define CPA_COMMIT() asm volatile("cp.async.commit_group;" ::: "memory")
#define CPA_WAIT(n)  asm volatile("cp.async.wait_group %0;" :: "n"(n) : "memory")

// ---------------- mma.sync / ldmatrix helpers (baseline PTX, sm_80+) --------
__device__ __forceinline__ void ldm_x4(uint32_t a[4], uint32_t addr){
    asm volatile("ldmatrix.sync.aligned.m8n8.x4.shared.b16 {%0,%1,%2,%3}, [%4];"
        : "=r"(a[0]), "=r"(a[1]), "=r"(a[2]), "=r"(a[3]) : "r"(addr));
}
__device__ __forceinline__ void ldm_x4t(uint32_t a[4], uint32_t addr){
    asm volatile("ldmatrix.sync.aligned.m8n8.x4.trans.shared.b16 {%0,%1,%2,%3}, [%4];"
        : "=r"(a[0]), "=r"(a[1]), "=r"(a[2]), "=r"(a[3]) : "r"(addr));
}
__device__ __forceinline__ void mma16816(float c[4], const uint32_t a[4], const uint32_t b[2]){
    asm volatile("mma.sync.aligned.m16n8k16.row.col.f32.f16.f16.f32 "
        "{%0,%1,%2,%3}, {%4,%5,%6,%7}, {%8,%9}, {%0,%1,%2,%3};"
        : "+f"(c[0]), "+f"(c[1]), "+f"(c[2]), "+f"(c[3])
        : "r"(a[0]), "r"(a[1]), "r"(a[2]), "r"(a[3]), "r"(b[0]), "r"(b[1]));
}

// ---------------- fold: W_eff = m_w @ w_w (fp16 out), b_eff ----------------
__global__ void k_fold(const float* __restrict__ wq_w, const float* __restrict__ wq_b,
                       const float* __restrict__ wk_w, const float* __restrict__ wk_b,
                       const float* __restrict__ wv_w, const float* __restrict__ wv_b,
                       const float* __restrict__ mq_w, const float* __restrict__ mq_b,
                       const float* __restrict__ mk_w, const float* __restrict__ mk_b){
    int r = blockIdx.x, e = threadIdx.x;
    if (r < 256){
        float acc = 0.f;
        for (int c = 0; c < 256; c++) acc += mq_w[r*256+c]*wq_w[c*64+e];
        g_Wh[r*64+e] = __float2half_rn(acc);
        if (e == 0){
            float bb = mq_b[r];
            for (int c = 0; c < 256; c++) bb += mq_w[r*256+c]*wq_b[c];
            g_bp[r] = bb;
        }
    } else if (r < 512){
        int rr = r - 256;
        float acc = 0.f;
        for (int c = 0; c < 256; c++) acc += mk_w[rr*256+c]*wk_w[c*64+e];
        g_Wh[r*64+e] = __float2half_rn(acc);
        if (e == 0){
            float bb = mk_b[rr];
            for (int c = 0; c < 256; c++) bb += mk_w[rr*256+c]*wk_b[c];
            g_bp[r] = bb;
        }
    } else {
        int rr = r - 512;
        g_Wh[r*64+e] = __float2half_rn(wv_w[rr*64+e]);
        if (e == 0) g_bp[r] = wv_b[rr];
    }
}

// ---------------- LayerNorm over E=64 -> fp16: one warp per row --------------
__global__ __launch_bounds__(256) void k_ln(const float* __restrict__ x,
                                            const float* __restrict__ g,
                                            const float* __restrict__ be){
    int t = threadIdx.x, lane = t & 31, w = t >> 5;
    size_t row = (size_t)blockIdx.x*8 + w;
    const float* xr = x + row*64;
    float x0 = xr[lane], x1 = xr[lane+32];
    float mean = wsum(x0+x1)*(1.f/64.f);
    float msq  = wsum(x0*x0+x1*x1)*(1.f/64.f);
    float rs = rsqrtf(msq - mean*mean + 1e-5f);
    __half* o = g_xh + row*64;
    o[lane]    = __float2half_rn((x0-mean)*rs*g[lane]    + be[lane]);
    o[lane+32] = __float2half_rn((x1-mean)*rs*g[lane+32] + be[lane+32]);
}

// ---------------- k_qkv: HMMA GEMM  [64 rows] x [256 cols], grid (256,3) -----
// blockIdx.y: 0 -> Q, 1 -> K, 2 -> V (no per-element branching)
__global__ __launch_bounds__(256) void k_qkv(){
    __shared__ __half sA[64*72];    // pitch 144 B
    __shared__ __half sB[256*72];
    int t = threadIdx.x, lane = t & 31, wid = t >> 5;
    int t4 = lane & 3, gq = lane >> 2;
    int wq = wid & 1, wd = wid >> 1;
    int m0 = blockIdx.x*64;
    int ny = blockIdx.y;
    uint32_t sa = smem_u32(sA), sbb = smem_u32(sB);
    for (int i = t; i < 512; i += 256){
        int r = i >> 3, c = i & 7;
        *(uint4*)((char*)sA + r*144 + c*16) =
            *(const uint4*)((const char*)(g_xh + ((size_t)(m0+r))*64) + c*16);
    }
    for (int i = t; i < 2048; i += 256){
        int r = i >> 3, c = i & 7;
        *(uint4*)((char*)sB + r*144 + c*16) =
            *(const uint4*)((const char*)(g_Wh + (size_t)(ny*256 + r)*64) + c*16);
    }
    __syncthreads();
    uint32_t lo16 = lane & 15, hi16 = lane >> 4;
    uint32_t aQb = sa + (uint32_t)(wq*32 + lo16)*144 + hi16*16;
    uint32_t kl  = (uint32_t)((lane & 7) + ((lane >> 4) << 3));
    uint32_t bWb = sbb + (uint32_t)(wd*64)*144 + kl*144 + (uint32_t)((lane >> 3) & 1)*16;

    float out[2][8][4] = {};
    #pragma unroll
    for (int ks = 0; ks < 4; ks++){
        uint32_t hk = (uint32_t)ks*32;
        uint32_t aq[2][4];
        ldm_x4(aq[0], aQb + hk);
        ldm_x4(aq[1], aQb + 16u*144 + hk);
        #pragma unroll
        for (int ng = 0; ng < 4; ng++){
            uint32_t kf[4];
            ldm_x4(kf, bWb + (uint32_t)(ng*16)*144 + hk);
            #pragma unroll
            for (int mb = 0; mb < 2; mb++){
                mma16816(out[mb][ng*2],   aq[mb], kf);
                mma16816(out[mb][ng*2+1], aq[mb], kf+2);
            }
        }
    }
    __half* dst = (ny == 0) ? g_q : (ny == 1 ? g_k : g_v);
    const float* bp = g_bp + ny*256;
    #pragma unroll
    for (int mb = 0; mb < 2; mb++){
        size_t rA = (size_t)m0 + (size_t)(wq*32 + mb*16 + gq);
        size_t rB = rA + 8;
        #pragma unroll
        for (int nt = 0; nt < 8; nt++){
            int col = wd*64 + nt*8 + 2*t4;
            float b0 = bp[col], b1 = bp[col+1];
            __half2 hA = __floats2half2_rn(out[mb][nt][0] + b0, out[mb][nt][1] + b1);
            __half2 hB = __floats2half2_rn(out[mb][nt][2] + b0, out[mb][nt][3] + b1);
            *(__half2*)&dst[rA*256 + col] = hA;
            *(__half2*)&dst[rB*256 + col] = hB;
        }
    }
}

// ---------------- k_score: 64-query CTAs, 2 CTAs/SM, grid 256 ----------------
#define SC_SQO 0
#define SC_SK0 33792
#define SC_SK1 67584
#define SC_SW0 101376
#define SC_SW1 101632
#define SC_SLO 101888
#define SC_SLW 105984
#define SC_SMEM 110080

__global__ void __launch_bounds__(256,2) k_score(const float* __restrict__ gw){
    extern __shared__ char sm[];
    uint32_t sb = smem_u32(sm);
    int t = threadIdx.x, lane = t & 31, wid = t >> 5;
    int t4 = lane & 3, gq = lane >> 2;
    int wq = wid & 1, wk = wid >> 1;
    int b = blockIdx.x >> 5, qt = blockIdx.x & 31;
    size_t qrow0 = (size_t)b*NN + (size_t)qt*64;
    int RB0 = (int)(qrow0 >> 4);
    const char*  qg  = (const char*)(g_q + qrow0*256);
    const char*  kgb = (const char*)(g_k + (size_t)b*NN*256);
    const float* wb  = gw + (size_t)b*NN;
    float* sL = (float*)(sm + SC_SLO);
    float* sLW = (float*)(sm + SC_SLW);

    for (int i = t; i < 2048; i += 256){
        int r = i >> 5, c = i & 31;
        cpa16(sb + SC_SK0 + r*528 + c*16, kgb + (size_t)r*512 + c*16);
    }
    if (t < 64) cpa4(sb + SC_SW0 + t*4, wb + t);
    CPA_COMMIT();
    for (int i = t; i < 2048; i += 256){
        int r = i >> 5, c = i & 31;
        *(uint4*)(sm + SC_SQO + r*528 + c*16) = *(const uint4*)(qg + r*512 + c*16);
    }

    uint32_t lo16 = lane & 15, hi16 = lane >> 4;
    uint32_t aQb = sb + SC_SQO + (uint32_t)(wq*32 + lo16)*528 + hi16*16;
    uint32_t kl  = (uint32_t)((lane & 7) + ((lane >> 4) << 3));

    float lacc[2][2][4], lwac[2][2][4];
    #pragma unroll
    for (int mb = 0; mb < 2; mb++)
        #pragma unroll
        for (int hf = 0; hf < 2; hf++)
            #pragma unroll
            for (int h = 0; h < 4; h++){ lacc[mb][hf][h] = 0.f; lwac[mb][hf][h] = 0.f; }

    for (int jt = 0; jt < 32; jt++){
        uint32_t koff = (jt & 1) ? SC_SK1 : SC_SK0;
        uint32_t woff = (jt & 1) ? SC_SW1 : SC_SW0;
        if (jt < 31){
            uint32_t kn = (jt & 1) ? SC_SK0 : SC_SK1;
            uint32_t wn = (jt & 1) ? SC_SW0 : SC_SW1;
            const char* src = kgb + (size_t)(jt+1)*32768;
            for (int i = t; i < 2048; i += 256){
                int r = i >> 5, c = i & 31;
                cpa16(sb + kn + r*528 + c*16, src + (size_t)r*512 + c*16);
            }
            if (t < 64) cpa4(sb + wn + t*4, wb + (jt+1)*64 + t);
            CPA_COMMIT();
            CPA_WAIT(1);
        } else {
            CPA_WAIT(0);
        }
        __syncthreads();
        const float* sw = (const float*)(sm + woff);
        uint32_t bKb = sb + koff + (uint32_t)(wk*16)*528 + kl*528 + (uint32_t)((lane >> 3) & 1)*16;
        #pragma unroll
        for (int h = 0; h < 4; h++){
            float sacc[2][2][4];
            #pragma unroll
            for (int mb = 0; mb < 2; mb++)
                #pragma unroll
                for (int nt = 0; nt < 2; nt++)
                    #pragma unroll
                    for (int q = 0; q < 4; q++) sacc[mb][nt][q] = 0.f;
            #pragma unroll
            for (int ks = 0; ks < 4; ks++){
                uint32_t hk = (uint32_t)(h*64 + ks*16)*2;
                uint32_t aq[2][4];
                ldm_x4(aq[0], aQb + hk);
                ldm_x4(aq[1], aQb + 16u*528 + hk);
                uint32_t kf[4];
                ldm_x4(kf, bKb + hk);
                #pragma unroll
                for (int mb = 0; mb < 2; mb++){
                    mma16816(sacc[mb][0], aq[mb], kf);
                    mma16816(sacc[mb][1], aq[mb], kf+2);
                }
            }
            #pragma unroll
            for (int mb = 0; mb < 2; mb++){
                size_t RB = (size_t)(RB0 + wq*2 + mb);
                uint32_t pk[4];
                #pragma unroll
                for (int nt = 0; nt < 2; nt++){
                    int kloc = wk*16 + nt*8 + 2*t4;
                    float w0 = sw[kloc], w1 = sw[kloc+1];
                    float e0 = ex2f(sacc[mb][nt][0]*CEXP);
                    float e1 = ex2f(sacc[mb][nt][1]*CEXP);
                    float e2 = ex2f(sacc[mb][nt][2]*CEXP);
                    float e3 = ex2f(sacc[mb][nt][3]*CEXP);
                    lacc[mb][0][h] += (w0 != 0.f ? e0 : 0.f) + (w1 != 0.f ? e1 : 0.f);
                    lacc[mb][1][h] += (w0 != 0.f ? e2 : 0.f) + (w1 != 0.f ? e3 : 0.f);
                    float ew0 = e0*w0, ew1 = e1*w1, ew2 = e2*w0, ew3 = e3*w1;
                    lwac[mb][0][h] += ew0 + ew1;
                    lwac[mb][1][h] += ew2 + ew3;
                    pk[nt*2]   = packbf2(ew0, ew1);
                    pk[nt*2+1] = packbf2(ew2, ew3);
                }
                int kb = jt*4 + wk;
                g_e[(((RB*128 + (size_t)kb)*4 + (size_t)h) << 5) + lane] =
                    make_uint4(pk[0], pk[1], pk[2], pk[3]);
            }
        }
        __syncthreads();
    }
    #pragma unroll
    for (int mb = 0; mb < 2; mb++)
        #pragma unroll
        for (int hf = 0; hf < 2; hf++)
            #pragma unroll
            for (int h = 0; h < 4; h++){
                float v = lacc[mb][hf][h];
                v += __shfl_xor_sync(0xffffffffu, v, 1);
                v += __shfl_xor_sync(0xffffffffu, v, 2);
                float u = lwac[mb][hf][h];
                u += __shfl_xor_sync(0xffffffffu, u, 1);
                u += __shfl_xor_sync(0xffffffffu, u, 2);
                if (t4 == 0){
                    int row = wq*32 + mb*16 + hf*8 + gq;
                    sL[(wk*64 + row)*4 + h] = v;
                    sLW[(wk*64 + row)*4 + h] = u;
                }
            }
    __syncthreads();
    if (wk == 0 && t4 == 0){
        #pragma unroll
        for (int mb = 0; mb < 2; mb++)
            #pragma unroll
            for (int hf = 0; hf < 2; hf++){
                int row = wq*32 + mb*16 + hf*8 + gq;
                float il[4], z = 0.f;
                #pragma unroll
                for (int h = 0; h < 4; h++){
                    float l = sL[row*4+h] + sL[(64+row)*4+h] + sL[(128+row)*4+h] + sL[(192+row)*4+h];
                    float lw = sLW[row*4+h] + sLW[(64+row)*4+h] + sLW[(128+row)*4+h] + sLW[(192+row)*4+h];
                    il[h] = 1.f / l;
                    z += lw * il[h];
                }
                g_il[qrow0 + row] = make_float4(il[0], il[1], il[2], il[3]);
                g_z[qrow0 + row] = 1.f / z;
            }
    }
}

// ---------------- k_av: 64-row CTAs, 2 CTAs/SM, grid 256 --------------------
#define AV_SV0 0
#define AV_SV1 33792
#define AV_SPO 67584
#define AV_SIL 75776
#define AV_SMEM 76800

__device__ __forceinline__ uint32_t mixfrag(uint32_t e0, uint32_t e1, uint32_t e2, uint32_t e3,
                                            float i0, float i1, float i2, float i3){
    float lo = i0*bflo(e0) + i1*bflo(e1) + i2*bflo(e2) + i3*bflo(e3);
    float hi = i0*bfhi(e0) + i1*bfhi(e1) + i2*bfhi(e2) + i3*bfhi(e3);
    __half2 p = __floats2half2_rn(lo, hi);
    return *(uint32_t*)&p;
}

__global__ void __launch_bounds__(256,2) k_av(){
    extern __shared__ char sm[];
    uint32_t sb = smem_u32(sm);
    int t = threadIdx.x, lane = t & 31, wid = t >> 5;
    int t4 = lane & 3, gq = lane >> 2;
    int wq = wid & 1, wd = wid >> 1;
    size_t row0 = (size_t)blockIdx.x*64;
    int b = blockIdx.x >> 5;
    int RB0 = (int)(row0 >> 4);
    const char* vgb = (const char*)(g_v + (size_t)b*NN*256);
    float4* silv = (float4*)(sm + AV_SIL);

    for (int i = t; i < 2048; i += 256){
        int r = i >> 5, c = i & 31;
        cpa16(sb + AV_SV0 + r*528 + c*16, vgb + (size_t)r*512 + c*16);
    }
    CPA_COMMIT();

    uint32_t lo16 = lane & 15, hi16 = lane >> 4;
    if (t < 64) silv[t] = g_il[row0 + (size_t)t];

    float out[2][8][4];
    #pragma unroll
    for (int mb = 0; mb < 2; mb++)
        #pragma unroll
        for (int nt = 0; nt < 8; nt++)
            #pragma unroll
            for (int q = 0; q < 4; q++) out[mb][nt][q] = 0.f;

    for (int jt = 0; jt < 32; jt++){
        uint32_t voff = (jt & 1) ? AV_SV1 : AV_SV0;
        if (jt < 31){
            uint32_t vn = (jt & 1) ? AV_SV0 : AV_SV1;
            const char* src = vgb + (size_t)(jt+1)*32768;
            for (int i = t; i < 2048; i += 256){
                int r = i >> 5, c = i & 31;
                cpa16(sb + vn + r*528 + c*16, src + (size_t)r*512 + c*16);
            }
            CPA_COMMIT();
            CPA_WAIT(1);
        } else {
            CPA_WAIT(0);
        }
        __syncthreads();
        #pragma unroll
        for (int uu = 0; uu < 2; uu++){
            int u = wid + uu*8;
            int RBl = u >> 2, kbl = u & 3;
            const uint4* ep = &g_e[((((size_t)(RB0 + RBl)*128 + (size_t)(jt*4 + kbl))*4) << 5) + lane];
            uint4 u0 = ep[0], u1 = ep[32], u2 = ep[64], u3 = ep[96];
            float4 a = silv[RBl*16 + gq];
            float4 c = silv[RBl*16 + 8 + gq];
            uint4 o;
            o.x = mixfrag(u0.x, u1.x, u2.x, u3.x, a.x, a.y, a.z, a.w);
            o.y = mixfrag(u0.y, u1.y, u2.y, u3.y, c.x, c.y, c.z, c.w);
            o.z = mixfrag(u0.z, u1.z, u2.z, u3.z, a.x, a.y, a.z, a.w);
            o.w = mixfrag(u0.w, u1.w, u2.w, u3.w, c.x, c.y, c.z, c.w);
            *(uint4*)(sm + AV_SPO + (u*32 + lane)*16) = o;
        }
        __syncthreads();
        uint32_t bVb = sb + voff + lo16*528 + (uint32_t)wd*128 + hi16*16;
        #pragma unroll
        for (int ks = 0; ks < 4; ks++){
            uint32_t aF[2][4];
            #pragma unroll
            for (int mb = 0; mb < 2; mb++){
                uint4 v4 = *(const uint4*)(sm + AV_SPO + ((((wq*2 + mb)*4 + ks)*32 + lane))*16);
                aF[mb][0] = v4.x; aF[mb][1] = v4.y; aF[mb][2] = v4.z; aF[mb][3] = v4.w;
            }
            #pragma unroll
            for (int dt2 = 0; dt2 < 4; dt2++){
                uint32_t vf[4];
                ldm_x4t(vf, bVb + (uint32_t)(ks*16)*528 + (uint32_t)dt2*32);
                mma16816(out[0][dt2*2],   aF[0], vf);
                mma16816(out[0][dt2*2+1], aF[0], vf+2);
                mma16816(out[1][dt2*2],   aF[1], vf);
                mma16816(out[1][dt2*2+1], aF[1], vf+2);
            }
        }
        __syncthreads();
    }
    #pragma unroll
    for (int mb = 0; mb < 2; mb++){
        size_t rA = row0 + (size_t)(wq*32 + mb*16 + gq);
        size_t rB = rA + 8;
        float izA = g_z[rA], izB = g_z[rB];
        #pragma unroll
        for (int nt = 0; nt < 8; nt++){
            int col = wd*64 + nt*8 + 2*t4;
            *(float2*)&g_av[rA*256 + col] = make_float2(out[mb][nt][0]*izA, out[mb][nt][1]*izA);
            *(float2*)&g_av[rB*256 + col] = make_float2(out[mb][nt][2]*izB, out[mb][nt][3]*izB);
        }
    }
}

// ---------------- k_tail: out1 = x + av@ow^T + ob; out = LN(out1 + sp(LN(out1)@fw^T + fb))
__global__ __launch_bounds__(256) void k_tail(const float* __restrict__ ow,
                                              const float* __restrict__ ob,
                                              const float* __restrict__ x,
                                              const float* __restrict__ g,
                                              const float* __restrict__ be,
                                              const float* __restrict__ fw,
                                              const float* __restrict__ fb,
                                              float* __restrict__ out){
    __shared__ float sA[64*68];
    __shared__ float sB[64*68];
    __shared__ float sy[8][64];
    int m0 = blockIdx.x*64;
    int t = threadIdx.x, lane = t & 31, w = t >> 5;
    int cg = t & 15, rg = t >> 4;
    float acc[4][4] = {};
    for (int kc = 0; kc < 256; kc += 64){
        __syncthreads();
        for (int i = t; i < 1024; i += 256){
            int r = i >> 4, c = i & 15;
            *(float4*)&sA[r*68 + c*4] = *(const float4*)&g_av[((size_t)(m0+r))*256 + kc + c*4];
            *(float4*)&sB[r*68 + c*4] = *(const float4*)&ow[r*256 + kc + c*4];
        }
        __syncthreads();
        #pragma unroll 4
        for (int e4 = 0; e4 < 16; e4++){
            float4 av[4], bv[4];
            #pragma unroll
            for (int i = 0; i < 4; i++) av[i] = *(const float4*)&sA[(rg+16*i)*68 + e4*4];
            #pragma unroll
            for (int j = 0; j < 4; j++) bv[j] = *(const float4*)&sB[(cg+16*j)*68 + e4*4];
            #pragma unroll
            for (int i = 0; i < 4; i++)
                #pragma unroll
                for (int j = 0; j < 4; j++)
                    acc[i][j] += av[i].x*bv[j].x + av[i].y*bv[j].y + av[i].z*bv[j].z + av[i].w*bv[j].w;
        }
    }
    __syncthreads();
    #pragma unroll
    for (int i = 0; i < 4; i++){
        int rl = rg + 16*i;
        size_t m = m0 + rl;
        #pragma unroll
        for (int j = 0; j < 4; j++){
            int n = cg + 16*j;
            sA[rl*68 + n] = acc[i][j] + ob[n] + x[m*64 + n];
        }
    }
    for (int i = t; i < 4096; i += 256) sB[(i>>6)*65 + (i&63)] = fw[i];
    __syncthreads();
    #pragma unroll 1
    for (int rr = 0; rr < 8; rr++){
        int rl = w*8 + rr;
        float o0 = sA[rl*68 + lane], o1 = sA[rl*68 + lane + 32];
        float mean = wsum(o0+o1)*(1.f/64.f);
        float msq  = wsum(o0*o0+o1*o1)*(1.f/64.f);
        float rs = rsqrtf(msq - mean*mean + 1e-5f);
        sy[w][lane]    = (o0-mean)*rs*g[lane]    + be[lane];
        sy[w][lane+32] = (o1-mean)*rs*g[lane+32] + be[lane+32];
        __syncwarp();
        float a0 = fb[lane], a1 = fb[lane+32];
        #pragma unroll 8
        for (int c = 0; c < 64; c++){
            float yv = sy[w][c];
            a0 += yv * sB[lane*65 + c];
            a1 += yv * sB[(lane+32)*65 + c];
        }
        float s0 = o0 + softplusf(a0);
        float s1 = o1 + softplusf(a1);
        float m2 = wsum(s0+s1)*(1.f/64.f);
        float q2 = wsum(s0*s0+s1*s1)*(1.f/64.f);
        float r2 = rsqrtf(q2 - m2*m2 + 1e-5f);
        size_t m = m0 + rl;
        out[m*64 + lane]    = (s0-m2)*r2*g[lane]    + be[lane];
        out[m*64 + lane+32] = (s1-m2)*r2*g[lane+32] + be[lane+32];
        __syncwarp();
    }
}

// ---------------- launch ----------------
extern "C" void kernel_launch(void* const* d_in, const int* in_sizes, int n_in,
                              void* d_out, int out_size){
    (void)in_sizes; (void)n_in; (void)out_size;
    const float* x     = (const float*)d_in[0];
    const float* wts   = (const float*)d_in[1];
    const float* ln_g  = (const float*)d_in[2];
    const float* ln_b  = (const float*)d_in[3];
    const float* wq_w  = (const float*)d_in[4];
    const float* wq_b  = (const float*)d_in[5];
    const float* wk_w  = (const float*)d_in[6];
    const float* wk_b  = (const float*)d_in[7];
    const float* wv_w  = (const float*)d_in[8];
    const float* wv_b  = (const float*)d_in[9];
    const float* mq_w  = (const float*)d_in[10];
    const float* mq_b  = (const float*)d_in[11];
    const float* mk_w  = (const float*)d_in[12];
    const float* mk_b  = (const float*)d_in[13];
    const float* out_w = (const float*)d_in[14];
    const float* out_b = (const float*)d_in[15];
    const float* ffn_w = (const float*)d_in[16];
    const float* ffn_b = (const float*)d_in[17];
    float* out = (float*)d_out;

    cudaFuncSetAttribute(k_score, cudaFuncAttributeMaxDynamicSharedMemorySize, SC_SMEM);
    cudaFuncSetAttribute(k_av,    cudaFuncAttributeMaxDynamicSharedMemorySize, AV_SMEM);

    k_fold<<<768, 64>>>(wq_w, wq_b, wk_w, wk_b, wv_w, wv_b, mq_w, mq_b, mk_w, mk_b);
    k_ln<<<ROWS/8, 256>>>(x, ln_g, ln_b);
    k_qkv<<<dim3(ROWS/64, 3), 256>>>();
    k_score<<<256, 256, SC_SMEM>>>(wts);
    k_av<<<256, 256, AV_SMEM>>>();
    k_tail<<<ROWS/64, 256>>>(out_w, out_b, x, ln_g, ln_b, ffn_w, ffn_b, out);
}

// round 10
// speedup vs baseline: 1.7301x; 1.0482x over previous
#include <cuda_runtime.h>
#include <cuda_fp16.h>
#include <cuda_bf16.h>
#include <math.h>
#include <stdint.h>

#define BB 8
#define NN 2048
#define EE 64
#define DD 256
#define ROWS (BB*NN)   // 16384

// ---------------- scratch (static device globals; no allocs) ----------------
__device__ __align__(16) __half g_xh[ROWS*EE];   // LN(x) in fp16
__device__ __align__(16) __half g_q[ROWS*DD];
__device__ __align__(16) __half g_k[ROWS*DD];
__device__ __align__(16) __half g_v[ROWS*DD];
// per-head masked weighted exponents, bf16, A-fragment-major:
// [rowblock16 0..1023][keyblock16-in-batch 0..127][head 0..3][lane 0..31] uint4
__device__ uint4 g_e[(size_t)1024*128*4*32];   // 256MB
__device__ float4 g_il[ROWS];                  // 1/l per head
__device__ float  g_z[ROWS];                   // 1/z
__device__ float g_av[ROWS*DD];
__device__ __align__(16) __half g_Wh[768*64];  // folded qkv weights, fp16
__device__ float g_bp[768];

#define CEXP 0.18033688f   // 0.125 * log2(e)

// ---------------- generic helpers ----------------
__device__ __forceinline__ float wsum(float v){
    v += __shfl_xor_sync(0xffffffffu, v, 16);
    v += __shfl_xor_sync(0xffffffffu, v, 8);
    v += __shfl_xor_sync(0xffffffffu, v, 4);
    v += __shfl_xor_sync(0xffffffffu, v, 2);
    v += __shfl_xor_sync(0xffffffffu, v, 1);
    return v;
}
__device__ __forceinline__ float softplusf(float x){
    if (x > 20.f) return x;
    return log1pf(expf(x));
}
__device__ __forceinline__ uint32_t smem_u32(const void* p){
    uint32_t a;
    asm("{ .reg .u64 t; cvta.to.shared.u64 t, %1; cvt.u32.u64 %0, t; }" : "=r"(a) : "l"(p));
    return a;
}
__device__ __forceinline__ float ex2f(float x){
    float r;
    asm("ex2.approx.f32 %0, %1;" : "=f"(r) : "f"(x));
    return r;
}
__device__ __forceinline__ uint32_t packbf2(float a, float b){
    __nv_bfloat162 h = __floats2bfloat162_rn(a, b);
    return *(uint32_t*)&h;
}
__device__ __forceinline__ float bflo(uint32_t u){ return __uint_as_float(u << 16); }
__device__ __forceinline__ float bfhi(uint32_t u){ return __uint_as_float(u & 0xFFFF0000u); }

// ---------------- cp.async helpers (sm_80+ baseline) ----------------
__device__ __forceinline__ void cpa16(uint32_t dst, const void* src){
    asm volatile("cp.async.cg.shared.global [%0], [%1], 16;" :: "r"(dst), "l"(src) : "memory");
}
__device__ __forceinline__ void cpa4(uint32_t dst, const void* src){
    asm volatile("cp.async.ca.shared.global [%0], [%1], 4;" :: "r"(dst), "l"(src) : "memory");
}
#define CPA_COMMIT() asm volatile("cp.async.commit_group;" ::: "memory")
#define CPA_WAIT(n)  asm volatile("cp.async.wait_group %0;" :: "n"(n) : "memory")

// ---------------- mma.sync / ldmatrix helpers (baseline PTX, sm_80+) --------
__device__ __forceinline__ void ldm_x4(uint32_t a[4], uint32_t addr){
    asm volatile("ldmatrix.sync.aligned.m8n8.x4.shared.b16 {%0,%1,%2,%3}, [%4];"
        : "=r"(a[0]), "=r"(a[1]), "=r"(a[2]), "=r"(a[3]) : "r"(addr));
}
__device__ __forceinline__ void ldm_x4t(uint32_t a[4], uint32_t addr){
    asm volatile("ldmatrix.sync.aligned.m8n8.x4.trans.shared.b16 {%0,%1,%2,%3}, [%4];"
        : "=r"(a[0]), "=r"(a[1]), "=r"(a[2]), "=r"(a[3]) : "r"(addr));
}
__device__ __forceinline__ void mma16816(float c[4], const uint32_t a[4], const uint32_t b[2]){
    asm volatile("mma.sync.aligned.m16n8k16.row.col.f32.f16.f16.f32 "
        "{%0,%1,%2,%3}, {%4,%5,%6,%7}, {%8,%9}, {%0,%1,%2,%3};"
        : "+f"(c[0]), "+f"(c[1]), "+f"(c[2]), "+f"(c[3])
        : "r"(a[0]), "r"(a[1]), "r"(a[2]), "r"(a[3]), "r"(b[0]), "r"(b[1]));
}

// ---------------- fold: W_eff = m_w @ w_w (fp16 out), b_eff ----------------
__global__ void k_fold(const float* __restrict__ wq_w, const float* __restrict__ wq_b,
                       const float* __restrict__ wk_w, const float* __restrict__ wk_b,
                       const float* __restrict__ wv_w, const float* __restrict__ wv_b,
                       const float* __restrict__ mq_w, const float* __restrict__ mq_b,
                       const float* __restrict__ mk_w, const float* __restrict__ mk_b){
    int r = blockIdx.x, e = threadIdx.x;
    if (r < 256){
        float acc = 0.f;
        for (int c = 0; c < 256; c++) acc += mq_w[r*256+c]*wq_w[c*64+e];
        g_Wh[r*64+e] = __float2half_rn(acc);
        if (e == 0){
            float bb = mq_b[r];
            for (int c = 0; c < 256; c++) bb += mq_w[r*256+c]*wq_b[c];
            g_bp[r] = bb;
        }
    } else if (r < 512){
        int rr = r - 256;
        float acc = 0.f;
        for (int c = 0; c < 256; c++) acc += mk_w[rr*256+c]*wk_w[c*64+e];
        g_Wh[r*64+e] = __float2half_rn(acc);
        if (e == 0){
            float bb = mk_b[rr];
            for (int c = 0; c < 256; c++) bb += mk_w[rr*256+c]*wk_b[c];
            g_bp[r] = bb;
        }
    } else {
        int rr = r - 512;
        g_Wh[r*64+e] = __float2half_rn(wv_w[rr*64+e]);
        if (e == 0) g_bp[r] = wv_b[rr];
    }
}

// ---------------- LayerNorm over E=64 -> fp16: one warp per row --------------
__global__ __launch_bounds__(256) void k_ln(const float* __restrict__ x,
                                            const float* __restrict__ g,
                                            const float* __restrict__ be){
    int t = threadIdx.x, lane = t & 31, w = t >> 5;
    size_t row = (size_t)blockIdx.x*8 + w;
    const float* xr = x + row*64;
    float x0 = xr[lane], x1 = xr[lane+32];
    float mean = wsum(x0+x1)*(1.f/64.f);
    float msq  = wsum(x0*x0+x1*x1)*(1.f/64.f);
    float rs = rsqrtf(msq - mean*mean + 1e-5f);
    __half* o = g_xh + row*64;
    o[lane]    = __float2half_rn((x0-mean)*rs*g[lane]    + be[lane]);
    o[lane+32] = __float2half_rn((x1-mean)*rs*g[lane+32] + be[lane+32]);
}

// ---------------- k_qkv: HMMA GEMM  [64 rows] x [256 cols], grid (256,3) -----
__global__ __launch_bounds__(256) void k_qkv(){
    __shared__ __half sA[64*72];    // pitch 144 B
    __shared__ __half sB[256*72];
    int t = threadIdx.x, lane = t & 31, wid = t >> 5;
    int t4 = lane & 3, gq = lane >> 2;
    int wq = wid & 1, wd = wid >> 1;
    int m0 = blockIdx.x*64;
    int ny = blockIdx.y;
    uint32_t sa = smem_u32(sA), sbb = smem_u32(sB);
    for (int i = t; i < 512; i += 256){
        int r = i >> 3, c = i & 7;
        *(uint4*)((char*)sA + r*144 + c*16) =
            *(const uint4*)((const char*)(g_xh + ((size_t)(m0+r))*64) + c*16);
    }
    for (int i = t; i < 2048; i += 256){
        int r = i >> 3, c = i & 7;
        *(uint4*)((char*)sB + r*144 + c*16) =
            *(const uint4*)((const char*)(g_Wh + (size_t)(ny*256 + r)*64) + c*16);
    }
    __syncthreads();
    uint32_t lo16 = lane & 15, hi16 = lane >> 4;
    uint32_t aQb = sa + (uint32_t)(wq*32 + lo16)*144 + hi16*16;
    uint32_t kl  = (uint32_t)((lane & 7) + ((lane >> 4) << 3));
    uint32_t bWb = sbb + (uint32_t)(wd*64)*144 + kl*144 + (uint32_t)((lane >> 3) & 1)*16;

    float out[2][8][4] = {};
    #pragma unroll
    for (int ks = 0; ks < 4; ks++){
        uint32_t hk = (uint32_t)ks*32;
        uint32_t aq[2][4];
        ldm_x4(aq[0], aQb + hk);
        ldm_x4(aq[1], aQb + 16u*144 + hk);
        #pragma unroll
        for (int ng = 0; ng < 4; ng++){
            uint32_t kf[4];
            ldm_x4(kf, bWb + (uint32_t)(ng*16)*144 + hk);
            #pragma unroll
            for (int mb = 0; mb < 2; mb++){
                mma16816(out[mb][ng*2],   aq[mb], kf);
                mma16816(out[mb][ng*2+1], aq[mb], kf+2);
            }
        }
    }
    __half* dst = (ny == 0) ? g_q : (ny == 1 ? g_k : g_v);
    const float* bp = g_bp + ny*256;
    #pragma unroll
    for (int mb = 0; mb < 2; mb++){
        size_t rA = (size_t)m0 + (size_t)(wq*32 + mb*16 + gq);
        size_t rB = rA + 8;
        #pragma unroll
        for (int nt = 0; nt < 8; nt++){
            int col = wd*64 + nt*8 + 2*t4;
            float b0 = bp[col], b1 = bp[col+1];
            __half2 hA = __floats2half2_rn(out[mb][nt][0] + b0, out[mb][nt][1] + b1);
            __half2 hB = __floats2half2_rn(out[mb][nt][2] + b0, out[mb][nt][3] + b1);
            *(__half2*)&dst[rA*256 + col] = hA;
            *(__half2*)&dst[rB*256 + col] = hB;
        }
    }
}

// ---------------- k_score: 64-query CTAs, warp = 32r x 32k x 2h --------------
// 256 threads = 8 warps: wq = wid&1 (32-row), wk = (wid>>1)&1 (32-key), wh = wid>>2 (2-head)
#define SC_SQO 0
#define SC_SK0 33792
#define SC_SK1 67584
#define SC_SW0 101376
#define SC_SW1 101632
#define SC_SLO 101888
#define SC_SLW 103936
#define SC_SMEM 105984

__global__ void __launch_bounds__(256,2) k_score(const float* __restrict__ gw){
    extern __shared__ char sm[];
    uint32_t sb = smem_u32(sm);
    int t = threadIdx.x, lane = t & 31, wid = t >> 5;
    int t4 = lane & 3, gq = lane >> 2;
    int wq = wid & 1, wk = (wid >> 1) & 1, wh = wid >> 2;
    int b = blockIdx.x >> 5, qt = blockIdx.x & 31;
    size_t qrow0 = (size_t)b*NN + (size_t)qt*64;
    int RB0 = (int)(qrow0 >> 4);
    const char*  qg  = (const char*)(g_q + qrow0*256);
    const char*  kgb = (const char*)(g_k + (size_t)b*NN*256);
    const float* wb  = gw + (size_t)b*NN;
    float* sL = (float*)(sm + SC_SLO);
    float* sLW = (float*)(sm + SC_SLW);

    // prefetch K tile 0 + w tile 0
    for (int i = t; i < 2048; i += 256){
        int r = i >> 5, c = i & 31;
        cpa16(sb + SC_SK0 + r*528 + c*16, kgb + (size_t)r*512 + c*16);
    }
    if (t < 64) cpa4(sb + SC_SW0 + t*4, wb + t);
    CPA_COMMIT();
    // Q tile resident (64 x 512B, pitch 528)
    for (int i = t; i < 2048; i += 256){
        int r = i >> 5, c = i & 31;
        *(uint4*)(sm + SC_SQO + r*528 + c*16) = *(const uint4*)(qg + r*512 + c*16);
    }

    uint32_t lo16 = lane & 15, hi16 = lane >> 4;
    uint32_t aQb = sb + SC_SQO + (uint32_t)(wq*32 + lo16)*528 + hi16*16;
    uint32_t kl  = (uint32_t)((lane & 7) + ((lane >> 4) << 3));

    float lacc[2][2][2], lwac[2][2][2];   // [mb][hf][hl]
    #pragma unroll
    for (int mb = 0; mb < 2; mb++)
        #pragma unroll
        for (int hf = 0; hf < 2; hf++)
            #pragma unroll
            for (int hl = 0; hl < 2; hl++){ lacc[mb][hf][hl] = 0.f; lwac[mb][hf][hl] = 0.f; }

    for (int jt = 0; jt < 32; jt++){
        uint32_t koff = (jt & 1) ? SC_SK1 : SC_SK0;
        uint32_t woff = (jt & 1) ? SC_SW1 : SC_SW0;
        if (jt < 31){
            uint32_t kn = (jt & 1) ? SC_SK0 : SC_SK1;
            uint32_t wn = (jt & 1) ? SC_SW0 : SC_SW1;
            const char* src = kgb + (size_t)(jt+1)*32768;
            for (int i = t; i < 2048; i += 256){
                int r = i >> 5, c = i & 31;
                cpa16(sb + kn + r*528 + c*16, src + (size_t)r*512 + c*16);
            }
            if (t < 64) cpa4(sb + wn + t*4, wb + (jt+1)*64 + t);
            CPA_COMMIT();
            CPA_WAIT(1);
        } else {
            CPA_WAIT(0);
        }
        __syncthreads();
        const float* sw = (const float*)(sm + woff);
        // hoist w + binary mask (reused across 2 heads x 2 row-groups)
        float wv[8], mv[8];
        #pragma unroll
        for (int nt = 0; nt < 4; nt++){
            int kloc = wk*32 + nt*8 + 2*t4;
            wv[2*nt]   = sw[kloc];
            wv[2*nt+1] = sw[kloc+1];
            mv[2*nt]   = (wv[2*nt]   != 0.f) ? 1.f : 0.f;
            mv[2*nt+1] = (wv[2*nt+1] != 0.f) ? 1.f : 0.f;
        }
        uint32_t bKb = sb + koff + (uint32_t)(wk*32)*528 + kl*528 + (uint32_t)((lane >> 3) & 1)*16;
        #pragma unroll
        for (int hl = 0; hl < 2; hl++){
            int h = wh*2 + hl;
            float sacc[2][4][4];
            #pragma unroll
            for (int mb = 0; mb < 2; mb++)
                #pragma unroll
                for (int nt = 0; nt < 4; nt++)
                    #pragma unroll
                    for (int q = 0; q < 4; q++) sacc[mb][nt][q] = 0.f;
            #pragma unroll
            for (int ks = 0; ks < 4; ks++){
                uint32_t hk = (uint32_t)(h*64 + ks*16)*2;
                uint32_t aq[2][4];
                ldm_x4(aq[0], aQb + hk);
                ldm_x4(aq[1], aQb + 16u*528 + hk);
                uint32_t kf0[4], kf1[4];
                ldm_x4(kf0, bKb + hk);
                ldm_x4(kf1, bKb + 16u*528 + hk);
                #pragma unroll
                for (int mb = 0; mb < 2; mb++){
                    mma16816(sacc[mb][0], aq[mb], kf0);
                    mma16816(sacc[mb][1], aq[mb], kf0+2);
                    mma16816(sacc[mb][2], aq[mb], kf1);
                    mma16816(sacc[mb][3], aq[mb], kf1+2);
                }
            }
            #pragma unroll
            for (int mb = 0; mb < 2; mb++){
                size_t RB = (size_t)(RB0 + wq*2 + mb);
                #pragma unroll
                for (int ntp = 0; ntp < 2; ntp++){
                    uint32_t pk[4];
                    #pragma unroll
                    for (int sub = 0; sub < 2; sub++){
                        int nt = ntp*2 + sub;
                        float e0 = ex2f(sacc[mb][nt][0]*CEXP);
                        float e1 = ex2f(sacc[mb][nt][1]*CEXP);
                        float e2 = ex2f(sacc[mb][nt][2]*CEXP);
                        float e3 = ex2f(sacc[mb][nt][3]*CEXP);
                        lacc[mb][0][hl] = fmaf(e0, mv[2*nt], fmaf(e1, mv[2*nt+1], lacc[mb][0][hl]));
                        lacc[mb][1][hl] = fmaf(e2, mv[2*nt], fmaf(e3, mv[2*nt+1], lacc[mb][1][hl]));
                        float ew0 = e0*wv[2*nt], ew1 = e1*wv[2*nt+1];
                        float ew2 = e2*wv[2*nt], ew3 = e3*wv[2*nt+1];
                        lwac[mb][0][hl] += ew0 + ew1;
                        lwac[mb][1][hl] += ew2 + ew3;
                        pk[sub*2]   = packbf2(ew0, ew1);
                        pk[sub*2+1] = packbf2(ew2, ew3);
                    }
                    int kb = jt*4 + wk*2 + ntp;
                    g_e[(((RB*128 + (size_t)kb)*4 + (size_t)h) << 5) + lane] =
                        make_uint4(pk[0], pk[1], pk[2], pk[3]);
                }
            }
        }
        __syncthreads();
    }
    // reduce l, lw across t4 quad, then across 2 wk warp-groups
    #pragma unroll
    for (int mb = 0; mb < 2; mb++)
        #pragma unroll
        for (int hf = 0; hf < 2; hf++)
            #pragma unroll
            for (int hl = 0; hl < 2; hl++){
                float v = lacc[mb][hf][hl];
                v += __shfl_xor_sync(0xffffffffu, v, 1);
                v += __shfl_xor_sync(0xffffffffu, v, 2);
                float u = lwac[mb][hf][hl];
                u += __shfl_xor_sync(0xffffffffu, u, 1);
                u += __shfl_xor_sync(0xffffffffu, u, 2);
                if (t4 == 0){
                    int row = wq*32 + mb*16 + hf*8 + gq;
                    int h = wh*2 + hl;
                    sL[(wk*64 + row)*4 + h] = v;
                    sLW[(wk*64 + row)*4 + h] = u;
                }
            }
    __syncthreads();
    if (wid < 2 && t4 == 0){   // wk == 0 && wh == 0, wq = wid
        #pragma unroll
        for (int mb = 0; mb < 2; mb++)
            #pragma unroll
            for (int hf = 0; hf < 2; hf++){
                int row = wq*32 + mb*16 + hf*8 + gq;
                float il[4], z = 0.f;
                #pragma unroll
                for (int h = 0; h < 4; h++){
                    float l  = sL[row*4+h]  + sL[(64+row)*4+h];
                    float lw = sLW[row*4+h] + sLW[(64+row)*4+h];
                    il[h] = 1.f / l;
                    z += lw * il[h];
                }
                g_il[qrow0 + row] = make_float4(il[0], il[1], il[2], il[3]);
                g_z[qrow0 + row] = 1.f / z;
            }
    }
}

// ---------------- k_av: 64-row CTAs, 2 CTAs/SM, grid 256 --------------------
#define AV_SV0 0
#define AV_SV1 33792
#define AV_SPO 67584
#define AV_SIL 75776
#define AV_SMEM 76800

__device__ __forceinline__ uint32_t mixfrag(uint32_t e0, uint32_t e1, uint32_t e2, uint32_t e3,
                                            float i0, float i1, float i2, float i3){
    float lo = i0*bflo(e0) + i1*bflo(e1) + i2*bflo(e2) + i3*bflo(e3);
    float hi = i0*bfhi(e0) + i1*bfhi(e1) + i2*bfhi(e2) + i3*bfhi(e3);
    __half2 p = __floats2half2_rn(lo, hi);
    return *(uint32_t*)&p;
}

__global__ void __launch_bounds__(256,2) k_av(){
    extern __shared__ char sm[];
    uint32_t sb = smem_u32(sm);
    int t = threadIdx.x, lane = t & 31, wid = t >> 5;
    int t4 = lane & 3, gq = lane >> 2;
    int wq = wid & 1, wd = wid >> 1;
    size_t row0 = (size_t)blockIdx.x*64;
    int b = blockIdx.x >> 5;
    int RB0 = (int)(row0 >> 4);
    const char* vgb = (const char*)(g_v + (size_t)b*NN*256);
    float4* silv = (float4*)(sm + AV_SIL);

    for (int i = t; i < 2048; i += 256){
        int r = i >> 5, c = i & 31;
        cpa16(sb + AV_SV0 + r*528 + c*16, vgb + (size_t)r*512 + c*16);
    }
    CPA_COMMIT();

    uint32_t lo16 = lane & 15, hi16 = lane >> 4;
    if (t < 64) silv[t] = g_il[row0 + (size_t)t];

    float out[2][8][4];
    #pragma unroll
    for (int mb = 0; mb < 2; mb++)
        #pragma unroll
        for (int nt = 0; nt < 8; nt++)
            #pragma unroll
            for (int q = 0; q < 4; q++) out[mb][nt][q] = 0.f;

    for (int jt = 0; jt < 32; jt++){
        uint32_t voff = (jt & 1) ? AV_SV1 : AV_SV0;
        if (jt < 31){
            uint32_t vn = (jt & 1) ? AV_SV0 : AV_SV1;
            const char* src = vgb + (size_t)(jt+1)*32768;
            for (int i = t; i < 2048; i += 256){
                int r = i >> 5, c = i & 31;
                cpa16(sb + vn + r*528 + c*16, src + (size_t)r*512 + c*16);
            }
            CPA_COMMIT();
            CPA_WAIT(1);
        } else {
            CPA_WAIT(0);
        }
        __syncthreads();
        #pragma unroll
        for (int uu = 0; uu < 2; uu++){
            int u = wid + uu*8;
            int RBl = u >> 2, kbl = u & 3;
            const uint4* ep = &g_e[((((size_t)(RB0 + RBl)*128 + (size_t)(jt*4 + kbl))*4) << 5) + lane];
            uint4 u0 = ep[0], u1 = ep[32], u2 = ep[64], u3 = ep[96];
            float4 a = silv[RBl*16 + gq];
            float4 c = silv[RBl*16 + 8 + gq];
            uint4 o;
            o.x = mixfrag(u0.x, u1.x, u2.x, u3.x, a.x, a.y, a.z, a.w);
            o.y = mixfrag(u0.y, u1.y, u2.y, u3.y, c.x, c.y, c.z, c.w);
            o.z = mixfrag(u0.z, u1.z, u2.z, u3.z, a.x, a.y, a.z, a.w);
            o.w = mixfrag(u0.w, u1.w, u2.w, u3.w, c.x, c.y, c.z, c.w);
            *(uint4*)(sm + AV_SPO + (u*32 + lane)*16) = o;
        }
        __syncthreads();
        uint32_t bVb = sb + voff + lo16*528 + (uint32_t)wd*128 + hi16*16;
        #pragma unroll
        for (int ks = 0; ks < 4; ks++){
            uint32_t aF[2][4];
            #pragma unroll
            for (int mb = 0; mb < 2; mb++){
                uint4 v4 = *(const uint4*)(sm + AV_SPO + ((((wq*2 + mb)*4 + ks)*32 + lane))*16);
                aF[mb][0] = v4.x; aF[mb][1] = v4.y; aF[mb][2] = v4.z; aF[mb][3] = v4.w;
            }
            #pragma unroll
            for (int dt2 = 0; dt2 < 4; dt2++){
                uint32_t vf[4];
                ldm_x4t(vf, bVb + (uint32_t)(ks*16)*528 + (uint32_t)dt2*32);
                mma16816(out[0][dt2*2],   aF[0], vf);
                mma16816(out[0][dt2*2+1], aF[0], vf+2);
                mma16816(out[1][dt2*2],   aF[1], vf);
                mma16816(out[1][dt2*2+1], aF[1], vf+2);
            }
        }
        __syncthreads();
    }
    #pragma unroll
    for (int mb = 0; mb < 2; mb++){
        size_t rA = row0 + (size_t)(wq*32 + mb*16 + gq);
        size_t rB = rA + 8;
        float izA = g_z[rA], izB = g_z[rB];
        #pragma unroll
        for (int nt = 0; nt < 8; nt++){
            int col = wd*64 + nt*8 + 2*t4;
            *(float2*)&g_av[rA*256 + col] = make_float2(out[mb][nt][0]*izA, out[mb][nt][1]*izA);
            *(float2*)&g_av[rB*256 + col] = make_float2(out[mb][nt][2]*izB, out[mb][nt][3]*izB);
        }
    }
}

// ---------------- k_tail: out1 = x + av@ow^T + ob; out = LN(out1 + sp(LN(out1)@fw^T + fb))
__global__ __launch_bounds__(256) void k_tail(const float* __restrict__ ow,
                                              const float* __restrict__ ob,
                                              const float* __restrict__ x,
                                              const float* __restrict__ g,
                                              const float* __restrict__ be,
                                              const float* __restrict__ fw,
                                              const float* __restrict__ fb,
                                              float* __restrict__ out){
    __shared__ float sA[64*68];
    __shared__ float sB[64*68];
    __shared__ float sy[8][64];
    int m0 = blockIdx.x*64;
    int t = threadIdx.x, lane = t & 31, w = t >> 5;
    int cg = t & 15, rg = t >> 4;
    float acc[4][4] = {};
    for (int kc = 0; kc < 256; kc += 64){
        __syncthreads();
        for (int i = t; i < 1024; i += 256){
            int r = i >> 4, c = i & 15;
            *(float4*)&sA[r*68 + c*4] = *(const float4*)&g_av[((size_t)(m0+r))*256 + kc + c*4];
            *(float4*)&sB[r*68 + c*4] = *(const float4*)&ow[r*256 + kc + c*4];
        }
        __syncthreads();
        #pragma unroll 4
        for (int e4 = 0; e4 < 16; e4++){
            float4 av[4], bv[4];
            #pragma unroll
            for (int i = 0; i < 4; i++) av[i] = *(const float4*)&sA[(rg+16*i)*68 + e4*4];
            #pragma unroll
            for (int j = 0; j < 4; j++) bv[j] = *(const float4*)&sB[(cg+16*j)*68 + e4*4];
            #pragma unroll
            for (int i = 0; i < 4; i++)
                #pragma unroll
                for (int j = 0; j < 4; j++)
                    acc[i][j] += av[i].x*bv[j].x + av[i].y*bv[j].y + av[i].z*bv[j].z + av[i].w*bv[j].w;
        }
    }
    __syncthreads();
    #pragma unroll
    for (int i = 0; i < 4; i++){
        int rl = rg + 16*i;
        size_t m = m0 + rl;
        #pragma unroll
        for (int j = 0; j < 4; j++){
            int n = cg + 16*j;
            sA[rl*68 + n] = acc[i][j] + ob[n] + x[m*64 + n];
        }
    }
    for (int i = t; i < 4096; i += 256) sB[(i>>6)*65 + (i&63)] = fw[i];
    __syncthreads();
    #pragma unroll 1
    for (int rr = 0; rr < 8; rr++){
        int rl = w*8 + rr;
        float o0 = sA[rl*68 + lane], o1 = sA[rl*68 + lane + 32];
        float mean = wsum(o0+o1)*(1.f/64.f);
        float msq  = wsum(o0*o0+o1*o1)*(1.f/64.f);
        float rs = rsqrtf(msq - mean*mean + 1e-5f);
        sy[w][lane]    = (o0-mean)*rs*g[lane]    + be[lane];
        sy[w][lane+32] = (o1-mean)*rs*g[lane+32] + be[lane+32];
        __syncwarp();
        float a0 = fb[lane], a1 = fb[lane+32];
        #pragma unroll 8
        for (int c = 0; c < 64; c++){
            float yv = sy[w][c];
            a0 += yv * sB[lane*65 + c];
            a1 += yv * sB[(lane+32)*65 + c];
        }
        float s0 = o0 + softplusf(a0);
        float s1 = o1 + softplusf(a1);
        float m2 = wsum(s0+s1)*(1.f/64.f);
        float q2 = wsum(s0*s0+s1*s1)*(1.f/64.f);
        float r2 = rsqrtf(q2 - m2*m2 + 1e-5f);
        size_t m = m0 + rl;
        out[m*64 + lane]    = (s0-m2)*r2*g[lane]    + be[lane];
        out[m*64 + lane+32] = (s1-m2)*r2*g[lane+32] + be[lane+32];
        __syncwarp();
    }
}

// ---------------- launch ----------------
extern "C" void kernel_launch(void* const* d_in, const int* in_sizes, int n_in,
                              void* d_out, int out_size){
    (void)in_sizes; (void)n_in; (void)out_size;
    const float* x     = (const float*)d_in[0];
    const float* wts   = (const float*)d_in[1];
    const float* ln_g  = (const float*)d_in[2];
    const float* ln_b  = (const float*)d_in[3];
    const float* wq_w  = (const float*)d_in[4];
    const float* wq_b  = (const float*)d_in[5];
    const float* wk_w  = (const float*)d_in[6];
    const float* wk_b  = (const float*)d_in[7];
    const float* wv_w  = (const float*)d_in[8];
    const float* wv_b  = (const float*)d_in[9];
    const float* mq_w  = (const float*)d_in[10];
    const float* mq_b  = (const float*)d_in[11];
    const float* mk_w  = (const float*)d_in[12];
    const float* mk_b  = (const float*)d_in[13];
    const float* out_w = (const float*)d_in[14];
    const float* out_b = (const float*)d_in[15];
    const float* ffn_w = (const float*)d_in[16];
    const float* ffn_b = (const float*)d_in[17];
    float* out = (float*)d_out;

    cudaFuncSetAttribute(k_score, cudaFuncAttributeMaxDynamicSharedMemorySize, SC_SMEM);
    cudaFuncSetAttribute(k_av,    cudaFuncAttributeMaxDynamicSharedMemorySize, AV_SMEM);

    k_fold<<<768, 64>>>(wq_w, wq_b, wk_w, wk_b, wv_w, wv_b, mq_w, mq_b, mk_w, mk_b);
    k_ln<<<ROWS/8, 256>>>(x, ln_g, ln_b);
    k_qkv<<<dim3(ROWS/64, 3), 256>>>();
    k_score<<<256, 256, SC_SMEM>>>(wts);
    k_av<<<256, 256, AV_SMEM>>>();
    k_tail<<<ROWS/64, 256>>>(out_w, out_b, x, ln_g, ln_b, ffn_w, ffn_b, out);
}

// round 11
// speedup vs baseline: 2.1166x; 1.2234x over previous
#include <cuda_runtime.h>
#include <cuda_fp16.h>
#include <cuda_bf16.h>
#include <math.h>
#include <stdint.h>

#define BB 8
#define NN 2048
#define EE 64
#define DD 256
#define ROWS (BB*NN)   // 16384

// ---------------- scratch (static device globals; no allocs) ----------------
__device__ __align__(16) __half g_xh[ROWS*EE];   // LN(x) in fp16
__device__ __align__(16) __half g_q[ROWS*DD];
__device__ __align__(16) __half g_k[ROWS*DD];
__device__ __align__(16) __half g_vo[ROWS*EE];   // V @ ow^T (+ ow@wvb), fp16, 64-wide
// per-head masked weighted exponents, bf16, A-fragment-major:
// [rowblock16 0..1023][keyblock16-in-batch 0..127][head 0..3][lane 0..31] uint4
__device__ uint4 g_e[(size_t)1024*128*4*32];   // 256MB
__device__ float4 g_il[ROWS];                  // 1/l per head
__device__ float  g_z[ROWS];                   // 1/z
__device__ float g_av[ROWS*EE];                // (C @ Vo)/z, 64-wide fp32
__device__ __align__(16) __half g_Wh[768*64];  // folded weights (q,k rows 0-511; Wvo 512-575; 0 pad)
__device__ float g_bp[768];

#define CEXP 0.18033688f   // 0.125 * log2(e)

// ---------------- generic helpers ----------------
__device__ __forceinline__ float wsum(float v){
    v += __shfl_xor_sync(0xffffffffu, v, 16);
    v += __shfl_xor_sync(0xffffffffu, v, 8);
    v += __shfl_xor_sync(0xffffffffu, v, 4);
    v += __shfl_xor_sync(0xffffffffu, v, 2);
    v += __shfl_xor_sync(0xffffffffu, v, 1);
    return v;
}
__device__ __forceinline__ float softplusf(float x){
    if (x > 20.f) return x;
    return log1pf(expf(x));
}
__device__ __forceinline__ uint32_t smem_u32(const void* p){
    uint32_t a;
    asm("{ .reg .u64 t; cvta.to.shared.u64 t, %1; cvt.u32.u64 %0, t; }" : "=r"(a) : "l"(p));
    return a;
}
__device__ __forceinline__ float ex2f(float x){
    float r;
    asm("ex2.approx.f32 %0, %1;" : "=f"(r) : "f"(x));
    return r;
}
__device__ __forceinline__ uint32_t packbf2(float a, float b){
    __nv_bfloat162 h = __floats2bfloat162_rn(a, b);
    return *(uint32_t*)&h;
}
__device__ __forceinline__ float bflo(uint32_t u){ return __uint_as_float(u << 16); }
__device__ __forceinline__ float bfhi(uint32_t u){ return __uint_as_float(u & 0xFFFF0000u); }

// ---------------- cp.async helpers (sm_80+ baseline) ----------------
__device__ __forceinline__ void cpa16(uint32_t dst, const void* src){
    asm volatile("cp.async.cg.shared.global [%0], [%1], 16;" :: "r"(dst), "l"(src) : "memory");
}
__device__ __forceinline__ void cpa4(uint32_t dst, const void* src){
    asm volatile("cp.async.ca.shared.global [%0], [%1], 4;" :: "r"(dst), "l"(src) : "memory");
}
#define CPA_COMMIT() asm volatile("cp.async.commit_group;" ::: "memory")
#define CPA_WAIT(n)  asm volatile("cp.async.wait_group %0;" :: "n"(n) : "memory")

// ---------------- mma.sync / ldmatrix helpers (baseline PTX, sm_80+) --------
__device__ __forceinline__ void ldm_x4(uint32_t a[4], uint32_t addr){
    asm volatile("ldmatrix.sync.aligned.m8n8.x4.shared.b16 {%0,%1,%2,%3}, [%4];"
        : "=r"(a[0]), "=r"(a[1]), "=r"(a[2]), "=r"(a[3]) : "r"(addr));
}
__device__ __forceinline__ void ldm_x4t(uint32_t a[4], uint32_t addr){
    asm volatile("ldmatrix.sync.aligned.m8n8.x4.trans.shared.b16 {%0,%1,%2,%3}, [%4];"
        : "=r"(a[0]), "=r"(a[1]), "=r"(a[2]), "=r"(a[3]) : "r"(addr));
}
__device__ __forceinline__ void mma16816(float c[4], const uint32_t a[4], const uint32_t b[2]){
    asm volatile("mma.sync.aligned.m16n8k16.row.col.f32.f16.f16.f32 "
        "{%0,%1,%2,%3}, {%4,%5,%6,%7}, {%8,%9}, {%0,%1,%2,%3};"
        : "+f"(c[0]), "+f"(c[1]), "+f"(c[2]), "+f"(c[3])
        : "r"(a[0]), "r"(a[1]), "r"(a[2]), "r"(a[3]), "r"(b[0]), "r"(b[1]));
}

// ---------------- fold: q/k effective weights + Wvo = ow @ wv ---------------
__global__ void k_fold(const float* __restrict__ wq_w, const float* __restrict__ wq_b,
                       const float* __restrict__ wk_w, const float* __restrict__ wk_b,
                       const float* __restrict__ wv_w, const float* __restrict__ wv_b,
                       const float* __restrict__ mq_w, const float* __restrict__ mq_b,
                       const float* __restrict__ mk_w, const float* __restrict__ mk_b,
                       const float* __restrict__ ow){
    int r = blockIdx.x, e = threadIdx.x;
    if (r < 256){
        float acc = 0.f;
        for (int c = 0; c < 256; c++) acc += mq_w[r*256+c]*wq_w[c*64+e];
        g_Wh[r*64+e] = __float2half_rn(acc);
        if (e == 0){
            float bb = mq_b[r];
            for (int c = 0; c < 256; c++) bb += mq_w[r*256+c]*wq_b[c];
            g_bp[r] = bb;
        }
    } else if (r < 512){
        int rr = r - 256;
        float acc = 0.f;
        for (int c = 0; c < 256; c++) acc += mk_w[rr*256+c]*wk_w[c*64+e];
        g_Wh[r*64+e] = __float2half_rn(acc);
        if (e == 0){
            float bb = mk_b[rr];
            for (int c = 0; c < 256; c++) bb += mk_w[rr*256+c]*wk_b[c];
            g_bp[r] = bb;
        }
    } else if (r < 576){
        int rr = r - 512;   // Wvo[rr][e] = sum_d ow[rr][d] * wv_w[d][e]
        float acc = 0.f;
        for (int d = 0; d < 256; d++) acc += ow[rr*256+d]*wv_w[d*64+e];
        g_Wh[r*64+e] = __float2half_rn(acc);
        if (e == 0){
            float bb = 0.f;
            for (int d = 0; d < 256; d++) bb += ow[rr*256+d]*wv_b[d];
            g_bp[r] = bb;
        }
    } else {
        g_Wh[r*64+e] = __float2half_rn(0.f);
        if (e == 0) g_bp[r] = 0.f;
    }
}

// ---------------- LayerNorm over E=64 -> fp16: one warp per row --------------
__global__ __launch_bounds__(256) void k_ln(const float* __restrict__ x,
                                            const float* __restrict__ g,
                                            const float* __restrict__ be){
    int t = threadIdx.x, lane = t & 31, w = t >> 5;
    size_t row = (size_t)blockIdx.x*8 + w;
    const float* xr = x + row*64;
    float x0 = xr[lane], x1 = xr[lane+32];
    float mean = wsum(x0+x1)*(1.f/64.f);
    float msq  = wsum(x0*x0+x1*x1)*(1.f/64.f);
    float rs = rsqrtf(msq - mean*mean + 1e-5f);
    __half* o = g_xh + row*64;
    o[lane]    = __float2half_rn((x0-mean)*rs*g[lane]    + be[lane]);
    o[lane+32] = __float2half_rn((x1-mean)*rs*g[lane+32] + be[lane+32]);
}

// ---------------- k_qkv: HMMA GEMM, grid (256,3): y=0 Q, y=1 K, y=2 Vo -------
__global__ __launch_bounds__(256) void k_qkv(){
    __shared__ __half sA[64*72];    // pitch 144 B
    __shared__ __half sB[256*72];
    int t = threadIdx.x, lane = t & 31, wid = t >> 5;
    int t4 = lane & 3, gq = lane >> 2;
    int wq = wid & 1, wd = wid >> 1;
    int m0 = blockIdx.x*64;
    int ny = blockIdx.y;
    uint32_t sa = smem_u32(sA), sbb = smem_u32(sB);
    for (int i = t; i < 512; i += 256){
        int r = i >> 3, c = i & 7;
        *(uint4*)((char*)sA + r*144 + c*16) =
            *(const uint4*)((const char*)(g_xh + ((size_t)(m0+r))*64) + c*16);
    }
    for (int i = t; i < 2048; i += 256){
        int r = i >> 3, c = i & 7;
        *(uint4*)((char*)sB + r*144 + c*16) =
            *(const uint4*)((const char*)(g_Wh + (size_t)(ny*256 + r)*64) + c*16);
    }
    __syncthreads();
    uint32_t lo16 = lane & 15, hi16 = lane >> 4;
    uint32_t aQb = sa + (uint32_t)(wq*32 + lo16)*144 + hi16*16;
    uint32_t kl  = (uint32_t)((lane & 7) + ((lane >> 4) << 3));
    uint32_t bWb = sbb + (uint32_t)(wd*64)*144 + kl*144 + (uint32_t)((lane >> 3) & 1)*16;

    float out[2][8][4] = {};
    #pragma unroll
    for (int ks = 0; ks < 4; ks++){
        uint32_t hk = (uint32_t)ks*32;
        uint32_t aq[2][4];
        ldm_x4(aq[0], aQb + hk);
        ldm_x4(aq[1], aQb + 16u*144 + hk);
        #pragma unroll
        for (int ng = 0; ng < 4; ng++){
            uint32_t kf[4];
            ldm_x4(kf, bWb + (uint32_t)(ng*16)*144 + hk);
            #pragma unroll
            for (int mb = 0; mb < 2; mb++){
                mma16816(out[mb][ng*2],   aq[mb], kf);
                mma16816(out[mb][ng*2+1], aq[mb], kf+2);
            }
        }
    }
    const float* bp = g_bp + ny*256;
    if (ny < 2){
        __half* dst = (ny == 0) ? g_q : g_k;
        #pragma unroll
        for (int mb = 0; mb < 2; mb++){
            size_t rA = (size_t)m0 + (size_t)(wq*32 + mb*16 + gq);
            size_t rB = rA + 8;
            #pragma unroll
            for (int nt = 0; nt < 8; nt++){
                int col = wd*64 + nt*8 + 2*t4;
                float b0 = bp[col], b1 = bp[col+1];
                __half2 hA = __floats2half2_rn(out[mb][nt][0] + b0, out[mb][nt][1] + b1);
                __half2 hB = __floats2half2_rn(out[mb][nt][2] + b0, out[mb][nt][3] + b1);
                *(__half2*)&dst[rA*256 + col] = hA;
                *(__half2*)&dst[rB*256 + col] = hB;
            }
        }
    } else if (wd == 0){
        // Vo: only cols 0..63 are real (Wvo rows 512..575; rest zero-padded)
        #pragma unroll
        for (int mb = 0; mb < 2; mb++){
            size_t rA = (size_t)m0 + (size_t)(wq*32 + mb*16 + gq);
            size_t rB = rA + 8;
            #pragma unroll
            for (int nt = 0; nt < 8; nt++){
                int col = nt*8 + 2*t4;
                float b0 = bp[col], b1 = bp[col+1];
                __half2 hA = __floats2half2_rn(out[mb][nt][0] + b0, out[mb][nt][1] + b1);
                __half2 hB = __floats2half2_rn(out[mb][nt][2] + b0, out[mb][nt][3] + b1);
                *(__half2*)&g_vo[rA*64 + col] = hA;
                *(__half2*)&g_vo[rB*64 + col] = hB;
            }
        }
    }
}

// ---------------- k_score: 64-query CTAs, warp = 32r x 32k x 2h --------------
#define SC_SQO 0
#define SC_SK0 33792
#define SC_SK1 67584
#define SC_SW0 101376
#define SC_SW1 101632
#define SC_SLO 101888
#define SC_SLW 103936
#define SC_SMEM 105984

__global__ void __launch_bounds__(256,2) k_score(const float* __restrict__ gw){
    extern __shared__ char sm[];
    uint32_t sb = smem_u32(sm);
    int t = threadIdx.x, lane = t & 31, wid = t >> 5;
    int t4 = lane & 3, gq = lane >> 2;
    int wq = wid & 1, wk = (wid >> 1) & 1, wh = wid >> 2;
    int b = blockIdx.x >> 5, qt = blockIdx.x & 31;
    size_t qrow0 = (size_t)b*NN + (size_t)qt*64;
    int RB0 = (int)(qrow0 >> 4);
    const char*  qg  = (const char*)(g_q + qrow0*256);
    const char*  kgb = (const char*)(g_k + (size_t)b*NN*256);
    const float* wb  = gw + (size_t)b*NN;
    float* sL = (float*)(sm + SC_SLO);
    float* sLW = (float*)(sm + SC_SLW);

    for (int i = t; i < 2048; i += 256){
        int r = i >> 5, c = i & 31;
        cpa16(sb + SC_SK0 + r*528 + c*16, kgb + (size_t)r*512 + c*16);
    }
    if (t < 64) cpa4(sb + SC_SW0 + t*4, wb + t);
    CPA_COMMIT();
    for (int i = t; i < 2048; i += 256){
        int r = i >> 5, c = i & 31;
        *(uint4*)(sm + SC_SQO + r*528 + c*16) = *(const uint4*)(qg + r*512 + c*16);
    }

    uint32_t lo16 = lane & 15, hi16 = lane >> 4;
    uint32_t aQb = sb + SC_SQO + (uint32_t)(wq*32 + lo16)*528 + hi16*16;
    uint32_t kl  = (uint32_t)((lane & 7) + ((lane >> 4) << 3));

    float lacc[2][2][2], lwac[2][2][2];
    #pragma unroll
    for (int mb = 0; mb < 2; mb++)
        #pragma unroll
        for (int hf = 0; hf < 2; hf++)
            #pragma unroll
            for (int hl = 0; hl < 2; hl++){ lacc[mb][hf][hl] = 0.f; lwac[mb][hf][hl] = 0.f; }

    for (int jt = 0; jt < 32; jt++){
        uint32_t koff = (jt & 1) ? SC_SK1 : SC_SK0;
        uint32_t woff = (jt & 1) ? SC_SW1 : SC_SW0;
        if (jt < 31){
            uint32_t kn = (jt & 1) ? SC_SK0 : SC_SK1;
            uint32_t wn = (jt & 1) ? SC_SW0 : SC_SW1;
            const char* src = kgb + (size_t)(jt+1)*32768;
            for (int i = t; i < 2048; i += 256){
                int r = i >> 5, c = i & 31;
                cpa16(sb + kn + r*528 + c*16, src + (size_t)r*512 + c*16);
            }
            if (t < 64) cpa4(sb + wn + t*4, wb + (jt+1)*64 + t);
            CPA_COMMIT();
            CPA_WAIT(1);
        } else {
            CPA_WAIT(0);
        }
        __syncthreads();
        const float* sw = (const float*)(sm + woff);
        float wv[8], mv[8];
        #pragma unroll
        for (int nt = 0; nt < 4; nt++){
            int kloc = wk*32 + nt*8 + 2*t4;
            wv[2*nt]   = sw[kloc];
            wv[2*nt+1] = sw[kloc+1];
            mv[2*nt]   = (wv[2*nt]   != 0.f) ? 1.f : 0.f;
            mv[2*nt+1] = (wv[2*nt+1] != 0.f) ? 1.f : 0.f;
        }
        uint32_t bKb = sb + koff + (uint32_t)(wk*32)*528 + kl*528 + (uint32_t)((lane >> 3) & 1)*16;
        #pragma unroll
        for (int hl = 0; hl < 2; hl++){
            int h = wh*2 + hl;
            float sacc[2][4][4];
            #pragma unroll
            for (int mb = 0; mb < 2; mb++)
                #pragma unroll
                for (int nt = 0; nt < 4; nt++)
                    #pragma unroll
                    for (int q = 0; q < 4; q++) sacc[mb][nt][q] = 0.f;
            #pragma unroll
            for (int ks = 0; ks < 4; ks++){
                uint32_t hk = (uint32_t)(h*64 + ks*16)*2;
                uint32_t aq[2][4];
                ldm_x4(aq[0], aQb + hk);
                ldm_x4(aq[1], aQb + 16u*528 + hk);
                uint32_t kf0[4], kf1[4];
                ldm_x4(kf0, bKb + hk);
                ldm_x4(kf1, bKb + 16u*528 + hk);
                #pragma unroll
                for (int mb = 0; mb < 2; mb++){
                    mma16816(sacc[mb][0], aq[mb], kf0);
                    mma16816(sacc[mb][1], aq[mb], kf0+2);
                    mma16816(sacc[mb][2], aq[mb], kf1);
                    mma16816(sacc[mb][3], aq[mb], kf1+2);
                }
            }
            #pragma unroll
            for (int mb = 0; mb < 2; mb++){
                size_t RB = (size_t)(RB0 + wq*2 + mb);
                #pragma unroll
                for (int ntp = 0; ntp < 2; ntp++){
                    uint32_t pk[4];
                    #pragma unroll
                    for (int sub = 0; sub < 2; sub++){
                        int nt = ntp*2 + sub;
                        float e0 = ex2f(sacc[mb][nt][0]*CEXP);
                        float e1 = ex2f(sacc[mb][nt][1]*CEXP);
                        float e2 = ex2f(sacc[mb][nt][2]*CEXP);
                        float e3 = ex2f(sacc[mb][nt][3]*CEXP);
                        lacc[mb][0][hl] = fmaf(e0, mv[2*nt], fmaf(e1, mv[2*nt+1], lacc[mb][0][hl]));
                        lacc[mb][1][hl] = fmaf(e2, mv[2*nt], fmaf(e3, mv[2*nt+1], lacc[mb][1][hl]));
                        float ew0 = e0*wv[2*nt], ew1 = e1*wv[2*nt+1];
                        float ew2 = e2*wv[2*nt], ew3 = e3*wv[2*nt+1];
                        lwac[mb][0][hl] += ew0 + ew1;
                        lwac[mb][1][hl] += ew2 + ew3;
                        pk[sub*2]   = packbf2(ew0, ew1);
                        pk[sub*2+1] = packbf2(ew2, ew3);
                    }
                    int kb = jt*4 + wk*2 + ntp;
                    g_e[(((RB*128 + (size_t)kb)*4 + (size_t)(wh*2 + hl)) << 5) + lane] =
                        make_uint4(pk[0], pk[1], pk[2], pk[3]);
                }
            }
        }
        __syncthreads();
    }
    #pragma unroll
    for (int mb = 0; mb < 2; mb++)
        #pragma unroll
        for (int hf = 0; hf < 2; hf++)
            #pragma unroll
            for (int hl = 0; hl < 2; hl++){
                float v = lacc[mb][hf][hl];
                v += __shfl_xor_sync(0xffffffffu, v, 1);
                v += __shfl_xor_sync(0xffffffffu, v, 2);
                float u = lwac[mb][hf][hl];
                u += __shfl_xor_sync(0xffffffffu, u, 1);
                u += __shfl_xor_sync(0xffffffffu, u, 2);
                if (t4 == 0){
                    int row = wq*32 + mb*16 + hf*8 + gq;
                    int h = wh*2 + hl;
                    sL[(wk*64 + row)*4 + h] = v;
                    sLW[(wk*64 + row)*4 + h] = u;
                }
            }
    __syncthreads();
    if (wid < 2 && t4 == 0){
        #pragma unroll
        for (int mb = 0; mb < 2; mb++)
            #pragma unroll
            for (int hf = 0; hf < 2; hf++){
                int row = wq*32 + mb*16 + hf*8 + gq;
                float il[4], z = 0.f;
                #pragma unroll
                for (int h = 0; h < 4; h++){
                    float l  = sL[row*4+h]  + sL[(64+row)*4+h];
                    float lw = sLW[row*4+h] + sLW[(64+row)*4+h];
                    il[h] = 1.f / l;
                    z += lw * il[h];
                }
                g_il[qrow0 + row] = make_float4(il[0], il[1], il[2], il[3]);
                g_z[qrow0 + row] = 1.f / z;
            }
    }
}

// ---------------- k_av: out = (C @ Vo)/z, 64-wide; warp = 32r x 16k ----------
// 256 threads = 8 warps: wq = wid&1 (32-row), kk = wid>>1 (16-key group in tile)
// K-dim split across kk -> smem reduction epilogue
#define AV_SV0 0
#define AV_SV1 9216
#define AV_SPO 18432
#define AV_SIL 26624
#define AV_SRD 27648
#define AV_SMEM 93184

__device__ __forceinline__ uint32_t mixfrag(uint32_t e0, uint32_t e1, uint32_t e2, uint32_t e3,
                                            float i0, float i1, float i2, float i3){
    float lo = i0*bflo(e0) + i1*bflo(e1) + i2*bflo(e2) + i3*bflo(e3);
    float hi = i0*bfhi(e0) + i1*bfhi(e1) + i2*bfhi(e2) + i3*bfhi(e3);
    __half2 p = __floats2half2_rn(lo, hi);
    return *(uint32_t*)&p;
}

__global__ void __launch_bounds__(256,2) k_av(){
    extern __shared__ char sm[];
    uint32_t sb = smem_u32(sm);
    int t = threadIdx.x, lane = t & 31, wid = t >> 5;
    int t4 = lane & 3, gq = lane >> 2;
    int wq = wid & 1, kk = wid >> 1;
    size_t row0 = (size_t)blockIdx.x*64;
    int b = blockIdx.x >> 5;
    int RB0 = (int)(row0 >> 4);
    const char* vgb = (const char*)(g_vo + (size_t)b*NN*64);
    float4* silv = (float4*)(sm + AV_SIL);

    // prefetch Vo tile 0 (64 keys x 128B, pitch 144)
    for (int i = t; i < 512; i += 256){
        int r = i >> 3, c = i & 7;
        cpa16(sb + AV_SV0 + r*144 + c*16, vgb + (size_t)r*128 + c*16);
    }
    CPA_COMMIT();

    uint32_t lo16 = lane & 15, hi16 = lane >> 4;
    if (t < 64) silv[t] = g_il[row0 + (size_t)t];

    float out[2][8][4];
    #pragma unroll
    for (int mb = 0; mb < 2; mb++)
        #pragma unroll
        for (int nt = 0; nt < 8; nt++)
            #pragma unroll
            for (int q = 0; q < 4; q++) out[mb][nt][q] = 0.f;

    for (int jt = 0; jt < 32; jt++){
        uint32_t voff = (jt & 1) ? AV_SV1 : AV_SV0;
        if (jt < 31){
            uint32_t vn = (jt & 1) ? AV_SV0 : AV_SV1;
            const char* src = vgb + (size_t)(jt+1)*8192;
            for (int i = t; i < 512; i += 256){
                int r = i >> 3, c = i & 7;
                cpa16(sb + vn + r*144 + c*16, src + (size_t)r*128 + c*16);
            }
            CPA_COMMIT();
            CPA_WAIT(1);
        } else {
            CPA_WAIT(0);
        }
        __syncthreads();
        // cooperative mix: 16 units (RBl 0..3 x kbl 0..3), each computed ONCE
        #pragma unroll
        for (int uu = 0; uu < 2; uu++){
            int u = wid + uu*8;
            int RBl = u >> 2, kbl = u & 3;
            const uint4* ep = &g_e[((((size_t)(RB0 + RBl)*128 + (size_t)(jt*4 + kbl))*4) << 5) + lane];
            uint4 u0 = ep[0], u1 = ep[32], u2 = ep[64], u3 = ep[96];
            float4 a = silv[RBl*16 + gq];
            float4 c = silv[RBl*16 + 8 + gq];
            uint4 o;
            o.x = mixfrag(u0.x, u1.x, u2.x, u3.x, a.x, a.y, a.z, a.w);
            o.y = mixfrag(u0.y, u1.y, u2.y, u3.y, c.x, c.y, c.z, c.w);
            o.z = mixfrag(u0.z, u1.z, u2.z, u3.z, a.x, a.y, a.z, a.w);
            o.w = mixfrag(u0.w, u1.w, u2.w, u3.w, c.x, c.y, c.z, c.w);
            *(uint4*)(sm + AV_SPO + (u*32 + lane)*16) = o;
        }
        __syncthreads();
        // MMA: warp handles its kk key-group (K=16) for all 64 output cols
        uint32_t aF[2][4];
        #pragma unroll
        for (int mb = 0; mb < 2; mb++){
            uint4 v4 = *(const uint4*)(sm + AV_SPO + ((((wq*2 + mb)*4 + kk)*32 + lane))*16);
            aF[mb][0] = v4.x; aF[mb][1] = v4.y; aF[mb][2] = v4.z; aF[mb][3] = v4.w;
        }
        uint32_t bVb = sb + voff + (uint32_t)(kk*16 + lo16)*144 + hi16*16;
        #pragma unroll
        for (int dt2 = 0; dt2 < 4; dt2++){
            uint32_t vf[4];
            ldm_x4t(vf, bVb + (uint32_t)dt2*32);
            mma16816(out[0][dt2*2],   aF[0], vf);
            mma16816(out[0][dt2*2+1], aF[0], vf+2);
            mma16816(out[1][dt2*2],   aF[1], vf);
            mma16816(out[1][dt2*2+1], aF[1], vf+2);
        }
        __syncthreads();
    }
    // reduction across kk groups via smem, then divide by z
    float* srd = (float*)(sm + AV_SRD);
    #pragma unroll
    for (int mb = 0; mb < 2; mb++){
        int rA = wq*32 + mb*16 + gq;
        int rB = rA + 8;
        #pragma unroll
        for (int nt = 0; nt < 8; nt++){
            int col = nt*8 + 2*t4;
            *(float2*)&srd[(kk*64 + rA)*64 + col] = make_float2(out[mb][nt][0], out[mb][nt][1]);
            *(float2*)&srd[(kk*64 + rB)*64 + col] = make_float2(out[mb][nt][2], out[mb][nt][3]);
        }
    }
    __syncthreads();
    for (int i = t; i < 1024; i += 256){
        int row = i >> 4, c4 = (i & 15)*4;
        float4 s0 = *(const float4*)&srd[(row)*64 + c4];
        float4 s1 = *(const float4*)&srd[(64 + row)*64 + c4];
        float4 s2 = *(const float4*)&srd[(128 + row)*64 + c4];
        float4 s3 = *(const float4*)&srd[(192 + row)*64 + c4];
        float iz = g_z[row0 + row];
        float4 o = make_float4((s0.x+s1.x+s2.x+s3.x)*iz, (s0.y+s1.y+s2.y+s3.y)*iz,
                               (s0.z+s1.z+s2.z+s3.z)*iz, (s0.w+s1.w+s2.w+s3.w)*iz);
        *(float4*)&g_av[(row0 + row)*64 + c4] = o;
    }
}

// ---------------- k_tail: out1 = x + av + ob; out = LN(out1 + sp(LN(out1)@fw^T + fb))
__global__ __launch_bounds__(256) void k_tail(const float* __restrict__ ob,
                                              const float* __restrict__ x,
                                              const float* __restrict__ g,
                                              const float* __restrict__ be,
                                              const float* __restrict__ fw,
                                              const float* __restrict__ fb,
                                              float* __restrict__ out){
    __shared__ float sA[64*68];
    __shared__ float sB[64*68];
    __shared__ float sy[8][64];
    int m0 = blockIdx.x*64;
    int t = threadIdx.x, lane = t & 31, w = t >> 5;
    for (int i = t; i < 1024; i += 256){
        int r = i >> 4, c = i & 15;
        float4 xv = *(const float4*)&x[((size_t)(m0+r))*64 + c*4];
        float4 av = *(const float4*)&g_av[((size_t)(m0+r))*64 + c*4];
        float4 obv = *(const float4*)&ob[c*4];
        sA[r*68 + c*4 + 0] = xv.x + av.x + obv.x;
        sA[r*68 + c*4 + 1] = xv.y + av.y + obv.y;
        sA[r*68 + c*4 + 2] = xv.z + av.z + obv.z;
        sA[r*68 + c*4 + 3] = xv.w + av.w + obv.w;
    }
    for (int i = t; i < 4096; i += 256) sB[(i>>6)*65 + (i&63)] = fw[i];
    __syncthreads();
    #pragma unroll 1
    for (int rr = 0; rr < 8; rr++){
        int rl = w*8 + rr;
        float o0 = sA[rl*68 + lane], o1 = sA[rl*68 + lane + 32];
        float mean = wsum(o0+o1)*(1.f/64.f);
        float msq  = wsum(o0*o0+o1*o1)*(1.f/64.f);
        float rs = rsqrtf(msq - mean*mean + 1e-5f);
        sy[w][lane]    = (o0-mean)*rs*g[lane]    + be[lane];
        sy[w][lane+32] = (o1-mean)*rs*g[lane+32] + be[lane+32];
        __syncwarp();
        float a0 = fb[lane], a1 = fb[lane+32];
        #pragma unroll 8
        for (int c = 0; c < 64; c++){
            float yv = sy[w][c];
            a0 += yv * sB[lane*65 + c];
            a1 += yv * sB[(lane+32)*65 + c];
        }
        float s0 = o0 + softplusf(a0);
        float s1 = o1 + softplusf(a1);
        float m2 = wsum(s0+s1)*(1.f/64.f);
        float q2 = wsum(s0*s0+s1*s1)*(1.f/64.f);
        float r2 = rsqrtf(q2 - m2*m2 + 1e-5f);
        size_t m = m0 + rl;
        out[m*64 + lane]    = (s0-m2)*r2*g[lane]    + be[lane];
        out[m*64 + lane+32] = (s1-m2)*r2*g[lane+32] + be[lane+32];
        __syncwarp();
    }
}

// ---------------- launch ----------------
extern "C" void kernel_launch(void* const* d_in, const int* in_sizes, int n_in,
                              void* d_out, int out_size){
    (void)in_sizes; (void)n_in; (void)out_size;
    const float* x     = (const float*)d_in[0];
    const float* wts   = (const float*)d_in[1];
    const float* ln_g  = (const float*)d_in[2];
    const float* ln_b  = (const float*)d_in[3];
    const float* wq_w  = (const float*)d_in[4];
    const float* wq_b  = (const float*)d_in[5];
    const float* wk_w  = (const float*)d_in[6];
    const float* wk_b  = (const float*)d_in[7];
    const float* wv_w  = (const float*)d_in[8];
    const float* wv_b  = (const float*)d_in[9];
    const float* mq_w  = (const float*)d_in[10];
    const float* mq_b  = (const float*)d_in[11];
    const float* mk_w  = (const float*)d_in[12];
    const float* mk_b  = (const float*)d_in[13];
    const float* out_w = (const float*)d_in[14];
    const float* out_b = (const float*)d_in[15];
    const float* ffn_w = (const float*)d_in[16];
    const float* ffn_b = (const float*)d_in[17];
    float* out = (float*)d_out;

    cudaFuncSetAttribute(k_score, cudaFuncAttributeMaxDynamicSharedMemorySize, SC_SMEM);
    cudaFuncSetAttribute(k_av,    cudaFuncAttributeMaxDynamicSharedMemorySize, AV_SMEM);

    k_fold<<<768, 64>>>(wq_w, wq_b, wk_w, wk_b, wv_w, wv_b, mq_w, mq_b, mk_w, mk_b, out_w);
    k_ln<<<ROWS/8, 256>>>(x, ln_g, ln_b);
    k_qkv<<<dim3(ROWS/64, 3), 256>>>();
    k_score<<<256, 256, SC_SMEM>>>(wts);
    k_av<<<256, 256, AV_SMEM>>>();
    k_tail<<<ROWS/64, 256>>>(out_b, x, ln_g, ln_b, ffn_w, ffn_b, out);
}